// round 3
// baseline (speedup 1.0000x reference)
#include <cuda_runtime.h>
#include <mma.h>
#include <math.h>

using namespace nvcuda;

#define B 4
#define M 2048
#define DMODEL 512
#define NHEAD 8
#define DHEAD 64
#define NTOK (B*M)          // 8192
#define BH (B*NHEAD)        // 32

// ---------------- scratch (device globals) ----------------
__device__ float g_q[BH * M * DHEAD];    // [b,h,m,dh], tf32-rounded, pre-scaled 1/8
__device__ float g_k[BH * M * DHEAD];    // tf32-rounded
__device__ float g_v[BH * M * DHEAD];    // tf32-rounded
__device__ float g_ao[NTOK * DMODEL];    // attention output, [b,m,d] fp32
__device__ float g_bias[M];              // log(exp(-d)+1e-12)
__device__ int   g_mask[NTOK];

// ---------------- mask dtype sniff + convert ----------------
__global__ void mask_convert(const unsigned int* __restrict__ w, int n) {
    __shared__ int not01, not0f;
    if (threadIdx.x == 0) { not01 = 0; not0f = 0; }
    __syncthreads();
    int b01 = 0, b0f = 0;
    for (int i = threadIdx.x; i < 2048; i += blockDim.x) {
        unsigned v = w[i];
        if (v > 1u) b01 = 1;
        if (v != 0u && v != 0x3F800000u) b0f = 1;
    }
    if (b01) atomicOr(&not01, 1);
    if (b0f) atomicOr(&not0f, 1);
    __syncthreads();
    int mode = (!not01) ? 1 : ((!not0f) ? 2 : 0); // 1=int32, 2=float32, 0=uint8
    for (int i = threadIdx.x; i < n; i += blockDim.x) {
        int v;
        if (mode == 1)      v = (((const int*)w)[i] != 0);
        else if (mode == 2) v = (((const float*)w)[i] != 0.0f);
        else                v = (((const unsigned char*)w)[i] != 0);
        g_mask[i] = v;
    }
}

__global__ void bias_init() {
    int i = blockIdx.x * blockDim.x + threadIdx.x;
    if (i < M) g_bias[i] = logf(expf(-(float)i) + 1e-12f);
}

// ---------------- QKV projection: wmma tf32, 128x128 C tile ----------------
#define GLD 36      // staging ld: 32 + 4
#define CLD 136     // C scratch ld: 128 + 8
#define GEMM_SMEM (128 * CLD * 4)   // 69632; staging (2*128*36*4=36864) aliases the front

__global__ __launch_bounds__(256) void qkv_gemm(
    const float* __restrict__ X,
    const float* __restrict__ Wq, const float* __restrict__ bq,
    const float* __restrict__ Wk, const float* __restrict__ bk,
    const float* __restrict__ Wv, const float* __restrict__ bv)
{
    extern __shared__ float sm[];
    float* Xs = sm;                 // [128][GLD] row-major [n][k]
    float* Ws = sm + 128 * GLD;     // [128][GLD] row-major [e][k]
    float* Cs = sm;                 // [128][CLD] epilogue scratch (aliases)

    const int z = blockIdx.z;
    const float* W    = (z == 0) ? Wq : (z == 1) ? Wk : Wv;
    const float* bias = (z == 0) ? bq : (z == 1) ? bk : bv;
    float* out        = (z == 0) ? g_q : (z == 1) ? g_k : g_v;
    const float oscale = (z == 0) ? 0.125f : 1.0f;

    const int t = threadIdx.x, warp = t >> 5;
    const int wm = warp >> 1, wn = warp & 1;   // 4 x 2 warps; warp tile 32(m) x 64(n)
    const int n0 = blockIdx.y << 7, e0 = blockIdx.x << 7;

    wmma::fragment<wmma::accumulator, 16, 16, 8, float> acc[2][4];
#pragma unroll
    for (int i = 0; i < 2; i++)
#pragma unroll
        for (int j = 0; j < 4; j++) wmma::fill_fragment(acc[i][j], 0.0f);

    for (int kk = 0; kk < DMODEL; kk += 32) {
        for (int i = t; i < 1024; i += 256) {
            int row = i >> 3, c4 = (i & 7) << 2;
            float4 xv = *(const float4*)&X[(size_t)(n0 + row) * DMODEL + kk + c4];
            float4 wv = *(const float4*)&W[(size_t)(e0 + row) * DMODEL + kk + c4];
            float* xd = &Xs[row * GLD + c4];
            float* wd = &Ws[row * GLD + c4];
            xd[0] = wmma::__float_to_tf32(xv.x); xd[1] = wmma::__float_to_tf32(xv.y);
            xd[2] = wmma::__float_to_tf32(xv.z); xd[3] = wmma::__float_to_tf32(xv.w);
            wd[0] = wmma::__float_to_tf32(wv.x); wd[1] = wmma::__float_to_tf32(wv.y);
            wd[2] = wmma::__float_to_tf32(wv.z); wd[3] = wmma::__float_to_tf32(wv.w);
        }
        __syncthreads();
#pragma unroll
        for (int kd = 0; kd < 32; kd += 8) {
            wmma::fragment<wmma::matrix_a, 16, 16, 8, wmma::precision::tf32, wmma::row_major> a[2];
            wmma::fragment<wmma::matrix_b, 16, 16, 8, wmma::precision::tf32, wmma::col_major> b[4];
#pragma unroll
            for (int i = 0; i < 2; i++)
                wmma::load_matrix_sync(a[i], &Xs[(wm * 32 + i * 16) * GLD + kd], GLD);
#pragma unroll
            for (int j = 0; j < 4; j++)
                wmma::load_matrix_sync(b[j], &Ws[(wn * 64 + j * 16) * GLD + kd], GLD);
#pragma unroll
            for (int i = 0; i < 2; i++)
#pragma unroll
                for (int j = 0; j < 4; j++) wmma::mma_sync(acc[i][j], a[i], b[j], acc[i][j]);
        }
        __syncthreads();
    }
#pragma unroll
    for (int i = 0; i < 2; i++)
#pragma unroll
        for (int j = 0; j < 4; j++)
            wmma::store_matrix_sync(&Cs[(wm * 32 + i * 16) * CLD + wn * 64 + j * 16],
                                    acc[i][j], CLD, wmma::mem_row_major);
    __syncthreads();
    for (int i = t; i < 16384; i += 256) {
        int row = i >> 7, c = i & 127;
        int n = n0 + row, e = e0 + c;
        int b = n >> 11, m = n & 2047;
        int hh = e >> 6, dh = e & 63;
        float v = wmma::__float_to_tf32((Cs[row * CLD + c] + bias[e]) * oscale);
        out[((((size_t)b << 3) + hh) * M + m) * DHEAD + dh] = v;
    }
}

// ---------------- attention: wmma tf32, static-max softmax ----------------
#define QLD 72
#define KLD 72
#define VLD 72
#define SLD 72
#define ATT_SMEM ((128*QLD + 64*KLD + 64*VLD + 128*SLD) * 4)   // 110592

__global__ __launch_bounds__(256) void attn_kernel() {
    extern __shared__ float sm[];
    float* Qs = sm;                        // [128][QLD], [m][d]
    float* Ks = Qs + 128 * QLD;            // [64][KLD], [n][d]
    float* Vs = Ks + 64 * KLD;             // [64][VLD], [n][d]
    float* Ss = Vs + 64 * VLD;             // [128][SLD], S then P, then O
    __shared__ float lrow[128];
    __shared__ float sbias[192];
    __shared__ int   msk[64];

    const int t = threadIdx.x, warp = t >> 5;
    const int wm = warp >> 1, wn = warp & 1;   // 4 x 2 warps; warp tile 32 x 32
    const int bh = blockIdx.y, b = bh >> 3, hh = bh & 7;
    const int m0 = blockIdx.x << 7;
    const float* qb = g_q + (size_t)bh * M * DHEAD;
    const float* kb = g_k + (size_t)bh * M * DHEAD;
    const float* vb = g_v + (size_t)bh * M * DHEAD;

    for (int i = t; i < 8192; i += 256) {
        int row = i >> 6, c = i & 63;
        Qs[row * QLD + c] = qb[(size_t)(m0 + row) * DHEAD + c];
    }
    if (t < 128) lrow[t] = 0.0f;

    wmma::fragment<wmma::accumulator, 16, 16, 8, float> oacc[2][2];
#pragma unroll
    for (int i = 0; i < 2; i++)
#pragma unroll
        for (int j = 0; j < 2; j++) wmma::fill_fragment(oacc[i][j], 0.0f);
    __syncthreads();

    for (int n0 = 0; n0 < M; n0 += 64) {
        for (int i = t; i < 4096; i += 256) {
            int row = i >> 6, c = i & 63;
            Ks[row * KLD + c] = kb[(size_t)(n0 + row) * DHEAD + c];
            Vs[row * VLD + c] = vb[(size_t)(n0 + row) * DHEAD + c];
        }
        if (t < 64) msk[t] = g_mask[b * M + n0 + t];
        for (int i = t; i < 191; i += 256) {
            int d = m0 - n0 + i - 63;
            sbias[i] = g_bias[d < 0 ? -d : d];
        }
        __syncthreads();

        // S = Q K^T (Q pre-scaled by 1/8)
        {
            wmma::fragment<wmma::accumulator, 16, 16, 8, float> sacc[2][2];
#pragma unroll
            for (int i = 0; i < 2; i++)
#pragma unroll
                for (int j = 0; j < 2; j++) wmma::fill_fragment(sacc[i][j], 0.0f);
#pragma unroll
            for (int d = 0; d < 64; d += 8) {
                wmma::fragment<wmma::matrix_a, 16, 16, 8, wmma::precision::tf32, wmma::row_major> a[2];
                wmma::fragment<wmma::matrix_b, 16, 16, 8, wmma::precision::tf32, wmma::col_major> kf[2];
#pragma unroll
                for (int i = 0; i < 2; i++)
                    wmma::load_matrix_sync(a[i], &Qs[(wm * 32 + i * 16) * QLD + d], QLD);
#pragma unroll
                for (int j = 0; j < 2; j++)
                    wmma::load_matrix_sync(kf[j], &Ks[(wn * 32 + j * 16) * KLD + d], KLD);
#pragma unroll
                for (int i = 0; i < 2; i++)
#pragma unroll
                    for (int j = 0; j < 2; j++) wmma::mma_sync(sacc[i][j], a[i], kf[j], sacc[i][j]);
            }
#pragma unroll
            for (int i = 0; i < 2; i++)
#pragma unroll
                for (int j = 0; j < 2; j++)
                    wmma::store_matrix_sync(&Ss[(wm * 32 + i * 16) * SLD + wn * 32 + j * 16],
                                            sacc[i][j], SLD, wmma::mem_row_major);
        }
        __syncthreads();

        // softmax (no max subtraction — S is provably small), P overwrites S
        {
            int row = t >> 1, c0 = (t & 1) << 5;
            float sum = 0.0f;
#pragma unroll
            for (int c = c0; c < c0 + 32; c++) {
                float sv = Ss[row * SLD + c];
                float p = msk[c] ? __expf(sv + sbias[row - c + 63]) : 0.0f;
                sum += p;
                Ss[row * SLD + c] = wmma::__float_to_tf32(p);
            }
            sum += __shfl_xor_sync(0xffffffffu, sum, 1);
            if ((t & 1) == 0) lrow[row] += sum;
        }
        __syncthreads();

        // O += P V
#pragma unroll
        for (int n = 0; n < 64; n += 8) {
            wmma::fragment<wmma::matrix_a, 16, 16, 8, wmma::precision::tf32, wmma::row_major> p[2];
            wmma::fragment<wmma::matrix_b, 16, 16, 8, wmma::precision::tf32, wmma::row_major> vf[2];
#pragma unroll
            for (int i = 0; i < 2; i++)
                wmma::load_matrix_sync(p[i], &Ss[(wm * 32 + i * 16) * SLD + n], SLD);
#pragma unroll
            for (int j = 0; j < 2; j++)
                wmma::load_matrix_sync(vf[j], &Vs[n * VLD + wn * 32 + j * 16], VLD);
#pragma unroll
            for (int i = 0; i < 2; i++)
#pragma unroll
                for (int j = 0; j < 2; j++) wmma::mma_sync(oacc[i][j], p[i], vf[j], oacc[i][j]);
        }
        __syncthreads();
    }

    // epilogue: O -> smem, normalize by l, write [b,m,d]
#pragma unroll
    for (int i = 0; i < 2; i++)
#pragma unroll
        for (int j = 0; j < 2; j++)
            wmma::store_matrix_sync(&Ss[(wm * 32 + i * 16) * SLD + wn * 32 + j * 16],
                                    oacc[i][j], SLD, wmma::mem_row_major);
    __syncthreads();
    float* ob = g_ao + (size_t)b * M * DMODEL + (size_t)hh * DHEAD;
    for (int i = t; i < 8192; i += 256) {
        int row = i >> 6, c = i & 63;
        float val = Ss[row * SLD + c] / lrow[row];
        ob[(size_t)(m0 + row) * DMODEL + c] = val;
    }
}

// ---------------- output projection + mask: wmma tf32 ----------------
__global__ __launch_bounds__(256) void oproj_gemm(
    const float* __restrict__ Wo, const float* __restrict__ bo,
    float* __restrict__ out)
{
    extern __shared__ float sm[];
    float* Xs = sm;
    float* Ws = sm + 128 * GLD;
    float* Cs = sm;

    const int t = threadIdx.x, warp = t >> 5;
    const int wm = warp >> 1, wn = warp & 1;
    const int n0 = blockIdx.y << 7, e0 = blockIdx.x << 7;

    wmma::fragment<wmma::accumulator, 16, 16, 8, float> acc[2][4];
#pragma unroll
    for (int i = 0; i < 2; i++)
#pragma unroll
        for (int j = 0; j < 4; j++) wmma::fill_fragment(acc[i][j], 0.0f);

    for (int kk = 0; kk < DMODEL; kk += 32) {
        for (int i = t; i < 1024; i += 256) {
            int row = i >> 3, c4 = (i & 7) << 2;
            float4 xv = *(const float4*)&g_ao[(size_t)(n0 + row) * DMODEL + kk + c4];
            float4 wv = *(const float4*)&Wo[(size_t)(e0 + row) * DMODEL + kk + c4];
            float* xd = &Xs[row * GLD + c4];
            float* wd = &Ws[row * GLD + c4];
            xd[0] = wmma::__float_to_tf32(xv.x); xd[1] = wmma::__float_to_tf32(xv.y);
            xd[2] = wmma::__float_to_tf32(xv.z); xd[3] = wmma::__float_to_tf32(xv.w);
            wd[0] = wmma::__float_to_tf32(wv.x); wd[1] = wmma::__float_to_tf32(wv.y);
            wd[2] = wmma::__float_to_tf32(wv.z); wd[3] = wmma::__float_to_tf32(wv.w);
        }
        __syncthreads();
#pragma unroll
        for (int kd = 0; kd < 32; kd += 8) {
            wmma::fragment<wmma::matrix_a, 16, 16, 8, wmma::precision::tf32, wmma::row_major> a[2];
            wmma::fragment<wmma::matrix_b, 16, 16, 8, wmma::precision::tf32, wmma::col_major> b[4];
#pragma unroll
            for (int i = 0; i < 2; i++)
                wmma::load_matrix_sync(a[i], &Xs[(wm * 32 + i * 16) * GLD + kd], GLD);
#pragma unroll
            for (int j = 0; j < 4; j++)
                wmma::load_matrix_sync(b[j], &Ws[(wn * 64 + j * 16) * GLD + kd], GLD);
#pragma unroll
            for (int i = 0; i < 2; i++)
#pragma unroll
                for (int j = 0; j < 4; j++) wmma::mma_sync(acc[i][j], a[i], b[j], acc[i][j]);
        }
        __syncthreads();
    }
#pragma unroll
    for (int i = 0; i < 2; i++)
#pragma unroll
        for (int j = 0; j < 4; j++)
            wmma::store_matrix_sync(&Cs[(wm * 32 + i * 16) * CLD + wn * 64 + j * 16],
                                    acc[i][j], CLD, wmma::mem_row_major);
    __syncthreads();
    for (int i = t; i < 16384; i += 256) {
        int row = i >> 7, c = i & 127;
        int n = n0 + row, e = e0 + c;
        float mk = (float)g_mask[n];
        out[(size_t)n * DMODEL + e] = (Cs[row * CLD + c] + bo[e]) * mk;
    }
}

// ---------------- launch ----------------
extern "C" void kernel_launch(void* const* d_in, const int* in_sizes, int n_in,
                              void* d_out, int out_size) {
    const float* h  = (const float*)d_in[0];
    const void*  pm = d_in[1];
    const float* Wq = (const float*)d_in[2];
    const float* bq = (const float*)d_in[3];
    const float* Wk = (const float*)d_in[4];
    const float* bk = (const float*)d_in[5];
    const float* Wv = (const float*)d_in[6];
    const float* bv = (const float*)d_in[7];
    const float* Wo = (const float*)d_in[8];
    const float* bo = (const float*)d_in[9];
    float* out = (float*)d_out;

    mask_convert<<<1, 256>>>((const unsigned int*)pm, NTOK);
    bias_init<<<8, 256>>>();

    cudaFuncSetAttribute(qkv_gemm, cudaFuncAttributeMaxDynamicSharedMemorySize, GEMM_SMEM);
    cudaFuncSetAttribute(oproj_gemm, cudaFuncAttributeMaxDynamicSharedMemorySize, GEMM_SMEM);
    cudaFuncSetAttribute(attn_kernel, cudaFuncAttributeMaxDynamicSharedMemorySize, ATT_SMEM);

    dim3 g1(DMODEL / 128, NTOK / 128, 3);
    qkv_gemm<<<g1, 256, GEMM_SMEM>>>(h, Wq, bq, Wk, bk, Wv, bv);

    dim3 g2(M / 128, BH);
    attn_kernel<<<g2, 256, ATT_SMEM>>>();

    dim3 g3(DMODEL / 128, NTOK / 128);
    oproj_gemm<<<g3, 256, GEMM_SMEM>>>(Wo, bo, out);
}

// round 5
// speedup vs baseline: 2.8116x; 2.8116x over previous
#include <cuda_runtime.h>
#include <math.h>

#define B 4
#define M 2048
#define DMODEL 512
#define NHEAD 8
#define DHEAD 64
#define NTOK (B*M)          // 8192
#define BH (B*NHEAD)        // 32

// ---------------- scratch (device globals) ----------------
__device__ float g_q[BH * M * DHEAD];    // [b,h,m,dh], tf32-rounded, pre-scaled 1/8
__device__ float g_k[BH * M * DHEAD];    // tf32-rounded
__device__ float g_v[BH * M * DHEAD];    // tf32-rounded
__device__ float g_ao[NTOK * DMODEL];    // attention output, [b,m,d] fp32
__device__ float g_bias[M];              // log(exp(-d)+1e-12)
__device__ int   g_mask[NTOK];

// ---------------- ptx helpers ----------------
__device__ __forceinline__ unsigned smem_u32(const void* p) {
    return (unsigned)__cvta_generic_to_shared(p);
}
__device__ __forceinline__ void cp16(unsigned d, const void* s) {
    asm volatile("cp.async.cg.shared.global [%0],[%1],16;\n" :: "r"(d), "l"(s) : "memory");
}
__device__ __forceinline__ void cp_commit() {
    asm volatile("cp.async.commit_group;\n" ::: "memory");
}
template<int N> __device__ __forceinline__ void cp_wait() {
    asm volatile("cp.async.wait_group %0;\n" :: "n"(N) : "memory");
}
__device__ __forceinline__ unsigned f2tf(float f) {
    unsigned u; asm("cvt.rna.tf32.f32 %0,%1;" : "=r"(u) : "f"(f)); return u;
}
// D += A*B, m16n8k8 tf32 (row.col)
__device__ __forceinline__ void mma8(float* c, const unsigned* a, const unsigned* b) {
    asm volatile(
        "mma.sync.aligned.m16n8k8.row.col.f32.tf32.tf32.f32 "
        "{%0,%1,%2,%3},{%4,%5,%6,%7},{%8,%9},{%0,%1,%2,%3};\n"
        : "+f"(c[0]), "+f"(c[1]), "+f"(c[2]), "+f"(c[3])
        : "r"(a[0]), "r"(a[1]), "r"(a[2]), "r"(a[3]), "r"(b[0]), "r"(b[1]));
}

// ---------------- mask dtype sniff + convert ----------------
__global__ void mask_convert(const unsigned int* __restrict__ w, int n) {
    __shared__ int not01, not0f;
    if (threadIdx.x == 0) { not01 = 0; not0f = 0; }
    __syncthreads();
    int b01 = 0, b0f = 0;
    for (int i = threadIdx.x; i < 2048; i += blockDim.x) {
        unsigned v = w[i];
        if (v > 1u) b01 = 1;
        if (v != 0u && v != 0x3F800000u) b0f = 1;
    }
    if (b01) atomicOr(&not01, 1);
    if (b0f) atomicOr(&not0f, 1);
    __syncthreads();
    int mode = (!not01) ? 1 : ((!not0f) ? 2 : 0); // 1=int32, 2=float32, 0=uint8
    for (int i = threadIdx.x; i < n; i += blockDim.x) {
        int v;
        if (mode == 1)      v = (((const int*)w)[i] != 0);
        else if (mode == 2) v = (((const float*)w)[i] != 0.0f);
        else                v = (((const unsigned char*)w)[i] != 0);
        g_mask[i] = v;
    }
}

__global__ void bias_init() {
    int i = blockIdx.x * blockDim.x + threadIdx.x;
    if (i < M) g_bias[i] = logf(expf(-(float)i) + 1e-12f);
}

// ---------------- QKV projection: raw mma tf32, 128x128 C tile ----------------
// 8 warps as 4(m) x 2(n); warp tile 32(m) x 64(n); k staged 32/iter, double-buffered.
#define GLD 36
#define GEMM_SMEM (4 * 128 * GLD * 4)   // 73728

__global__ __launch_bounds__(256) void qkv_gemm(
    const float* __restrict__ X,
    const float* __restrict__ Wq, const float* __restrict__ bq,
    const float* __restrict__ Wk, const float* __restrict__ bk,
    const float* __restrict__ Wv, const float* __restrict__ bv)
{
    extern __shared__ float sm[];
    float* Xs[2] = { sm,                 sm + 128 * GLD };
    float* Ws[2] = { sm + 2 * 128 * GLD, sm + 3 * 128 * GLD };

    const int z = blockIdx.z;
    const float* W    = (z == 0) ? Wq : (z == 1) ? Wk : Wv;
    const float* bias = (z == 0) ? bq : (z == 1) ? bk : bv;
    float* out        = (z == 0) ? g_q : (z == 1) ? g_k : g_v;
    const float oscale = (z == 0) ? 0.125f : 1.0f;

    const int t = threadIdx.x, warp = t >> 5, lane = t & 31;
    const int g = lane >> 2, q = lane & 3;
    const int wm = warp >> 1, wn = warp & 1;
    const int n0 = blockIdx.y << 7, e0 = blockIdx.x << 7;

    const int srow = t >> 3, sc4 = (t & 7) << 2;   // base row 0..31, col-of-4

    float acc[2][8][4] = {};
    float4 xr[4], wr[4];

    auto ldg = [&](int kk) {
#pragma unroll
        for (int j = 0; j < 4; j++) {
            int row = srow + j * 32;
            xr[j] = *(const float4*)&X[(size_t)(n0 + row) * DMODEL + kk + sc4];
            wr[j] = *(const float4*)&W[(size_t)(e0 + row) * DMODEL + kk + sc4];
        }
    };
    auto sts = [&](int buf) {
#pragma unroll
        for (int j = 0; j < 4; j++) {
            int row = srow + j * 32;
            float* xd = Xs[buf] + row * GLD + sc4;
            float* wd = Ws[buf] + row * GLD + sc4;
            float4 xv = xr[j], wv = wr[j];
            xd[0] = __uint_as_float(f2tf(xv.x)); xd[1] = __uint_as_float(f2tf(xv.y));
            xd[2] = __uint_as_float(f2tf(xv.z)); xd[3] = __uint_as_float(f2tf(xv.w));
            wd[0] = __uint_as_float(f2tf(wv.x)); wd[1] = __uint_as_float(f2tf(wv.y));
            wd[2] = __uint_as_float(f2tf(wv.z)); wd[3] = __uint_as_float(f2tf(wv.w));
        }
    };

    ldg(0); sts(0); __syncthreads();
    for (int it = 0; it < 16; it++) {
        if (it < 15) ldg((it + 1) * 32);
        const int buf = it & 1;
#pragma unroll
        for (int kc = 0; kc < 4; kc++) {
            unsigned af[2][4], bf[8][2];
#pragma unroll
            for (int mf = 0; mf < 2; mf++) {
                const float* ap = Xs[buf] + (wm * 32 + mf * 16 + g) * GLD + kc * 8 + q;
                af[mf][0] = __float_as_uint(ap[0]);
                af[mf][1] = __float_as_uint(ap[8 * GLD]);
                af[mf][2] = __float_as_uint(ap[4]);
                af[mf][3] = __float_as_uint(ap[8 * GLD + 4]);
            }
#pragma unroll
            for (int nf = 0; nf < 8; nf++) {
                const float* bp = Ws[buf] + (wn * 64 + nf * 8 + g) * GLD + kc * 8 + q;
                bf[nf][0] = __float_as_uint(bp[0]);
                bf[nf][1] = __float_as_uint(bp[4]);
            }
#pragma unroll
            for (int mf = 0; mf < 2; mf++)
#pragma unroll
                for (int nf = 0; nf < 8; nf++) mma8(acc[mf][nf], af[mf], bf[nf]);
        }
        if (it < 15) { sts((it + 1) & 1); __syncthreads(); }
    }

    // epilogue: direct to [b,h,m,dh], tf32-rounded
#pragma unroll
    for (int mf = 0; mf < 2; mf++) {
        int ntA = n0 + wm * 32 + mf * 16 + g;
        int ntB = ntA + 8;
#pragma unroll
        for (int nf = 0; nf < 8; nf++) {
            int e = e0 + wn * 64 + nf * 8 + 2 * q;
            int hh = e >> 6, dh = e & 63;
            float b0v = bias[e], b1v = bias[e + 1];
            {
                int bb_ = ntA >> 11, mm = ntA & 2047;
                float2 r;
                r.x = __uint_as_float(f2tf((acc[mf][nf][0] + b0v) * oscale));
                r.y = __uint_as_float(f2tf((acc[mf][nf][1] + b1v) * oscale));
                *(float2*)&out[(((size_t)bb_ * 8 + hh) * M + mm) * DHEAD + dh] = r;
            }
            {
                int bb_ = ntB >> 11, mm = ntB & 2047;
                float2 r;
                r.x = __uint_as_float(f2tf((acc[mf][nf][2] + b0v) * oscale));
                r.y = __uint_as_float(f2tf((acc[mf][nf][3] + b1v) * oscale));
                *(float2*)&out[(((size_t)bb_ * 8 + hh) * M + mm) * DHEAD + dh] = r;
            }
        }
    }
}

// ---------------- attention: raw mma tf32, register-resident flash ----------------
// 8 warps, each owns 16 Q rows of a 128-row tile. 64-key tiles, cp.async double buffer.
#define KLD 68   // 68 % 32 == 4 -> (g*KLD+q) conflict-free
#define VLD 72   // 72 % 32 == 8 -> (q*VLD+g) conflict-free
#define ATT_SMEM ((2*64*KLD + 2*64*VLD + 2048 + 2048) * 4)   // 88064

__global__ __launch_bounds__(256) void attn_kernel() {
    extern __shared__ float sm[];
    float* Ks0   = sm;                                 // [2][64][KLD]
    float* Vs0   = sm + 2 * 64 * KLD;                  // [2][64][VLD]
    float* sbias = sm + 2 * 64 * KLD + 2 * 64 * VLD;   // [2048]
    float* madd  = sbias + 2048;                       // [2048]

    const int t = threadIdx.x, warp = t >> 5, lane = t & 31;
    const int g = lane >> 2, q = lane & 3;
    const int bh = blockIdx.y, b = bh >> 3, hh = bh & 7;
    const int m0 = blockIdx.x << 7;
    const float* qb = g_q + (size_t)bh * M * DHEAD;
    const float* kb = g_k + (size_t)bh * M * DHEAD;
    const float* vb = g_v + (size_t)bh * M * DHEAD;

    // prologue: bias + additive-mask tables (synced by first tile barrier)
    for (int i = t; i < 2048; i += 256) {
        sbias[i] = g_bias[i];
        madd[i]  = g_mask[b * M + i] ? 0.0f : -1e9f;
    }

    // Q fragments (resident all kernel)
    const int mw = m0 + warp * 16;
    unsigned qf[8][4];
    {
        const float* q0 = qb + (size_t)(mw + g) * DHEAD;
        const float* q1 = qb + (size_t)(mw + g + 8) * DHEAD;
#pragma unroll
        for (int kc = 0; kc < 8; kc++) {
            qf[kc][0] = __float_as_uint(q0[kc * 8 + q]);
            qf[kc][1] = __float_as_uint(q1[kc * 8 + q]);
            qf[kc][2] = __float_as_uint(q0[kc * 8 + q + 4]);
            qf[kc][3] = __float_as_uint(q1[kc * 8 + q + 4]);
        }
    }

    float oacc[8][4] = {};
    float l0 = 0.0f, l1 = 0.0f;

    auto stage = [&](int tile, int buf) {
        const float* ksrc = kb + (size_t)(tile * 64) * DHEAD;
        const float* vsrc = vb + (size_t)(tile * 64) * DHEAD;
        float* kd = Ks0 + buf * 64 * KLD;
        float* vd = Vs0 + buf * 64 * VLD;
#pragma unroll
        for (int j = 0; j < 4; j++) {
            int ck = t + j * 256;                  // 0..1023
            int row = ck >> 4, c16 = ck & 15;
            cp16(smem_u32(kd + row * KLD) + c16 * 16, ksrc + row * 64 + c16 * 4);
            cp16(smem_u32(vd + row * VLD) + c16 * 16, vsrc + row * 64 + c16 * 4);
        }
    };

    stage(0, 0); cp_commit();

    const int src0 = (lane & ~3) | (q >> 1);
    const int src1 = src0 + 2;
    const bool odd = (q & 1);

    for (int tile = 0; tile < 32; tile++) {
        if (tile < 31) { stage(tile + 1, (tile + 1) & 1); cp_commit(); }
        if (tile < 31) cp_wait<1>(); else cp_wait<0>();
        __syncthreads();

        const float* Kst = Ks0 + (tile & 1) * 64 * KLD;
        const float* Vst = Vs0 + (tile & 1) * 64 * VLD;
        const int n0 = tile * 64;

        // ---- S = Q K^T ----
        float sacc[8][4] = {};
#pragma unroll
        for (int kc = 0; kc < 8; kc++) {
            unsigned bb[8][2];
#pragma unroll
            for (int nf = 0; nf < 8; nf++) {
                const float* kp = Kst + (nf * 8 + g) * KLD + kc * 8 + q;
                bb[nf][0] = __float_as_uint(kp[0]);
                bb[nf][1] = __float_as_uint(kp[4]);
            }
#pragma unroll
            for (int nf = 0; nf < 8; nf++) mma8(sacc[nf], qf[kc], bb[nf]);
        }

        // ---- softmax (static max): P = exp(S + bias + maskadd), tf32-rounded ----
        const int mg0 = mw + g, mg1 = mw + g + 8;
#pragma unroll
        for (int nf = 0; nf < 8; nf++) {
            int n_ = n0 + nf * 8 + 2 * q;
            float ma0 = madd[n_], ma1 = madd[n_ + 1];
            int d00 = abs(mg0 - n_), d01 = abs(mg0 - n_ - 1);
            int d10 = abs(mg1 - n_), d11 = abs(mg1 - n_ - 1);
            unsigned u0 = f2tf(__expf(sacc[nf][0] + sbias[d00] + ma0));
            unsigned u1 = f2tf(__expf(sacc[nf][1] + sbias[d01] + ma1));
            unsigned u2 = f2tf(__expf(sacc[nf][2] + sbias[d10] + ma0));
            unsigned u3 = f2tf(__expf(sacc[nf][3] + sbias[d11] + ma1));
            float p0 = __uint_as_float(u0), p1 = __uint_as_float(u1);
            float p2 = __uint_as_float(u2), p3 = __uint_as_float(u3);
            l0 += p0 + p1;
            l1 += p2 + p3;
            sacc[nf][0] = p0; sacc[nf][1] = p1; sacc[nf][2] = p2; sacc[nf][3] = p3;
        }

        // ---- O += P V (C-frag -> A-frag via shfl, V B-frags from smem) ----
#pragma unroll
        for (int kc = 0; kc < 8; kc++) {
            float c0 = sacc[kc][0], c1 = sacc[kc][1], c2 = sacc[kc][2], c3 = sacc[kc][3];
            float x0 = __shfl_sync(0xffffffffu, c0, src0);
            float x1 = __shfl_sync(0xffffffffu, c1, src0);
            float x2 = __shfl_sync(0xffffffffu, c2, src0);
            float x3 = __shfl_sync(0xffffffffu, c3, src0);
            float y0 = __shfl_sync(0xffffffffu, c0, src1);
            float y1 = __shfl_sync(0xffffffffu, c1, src1);
            float y2 = __shfl_sync(0xffffffffu, c2, src1);
            float y3 = __shfl_sync(0xffffffffu, c3, src1);
            unsigned pa[4];
            pa[0] = __float_as_uint(odd ? x1 : x0);
            pa[1] = __float_as_uint(odd ? x3 : x2);
            pa[2] = __float_as_uint(odd ? y1 : y0);
            pa[3] = __float_as_uint(odd ? y3 : y2);
            const float* vrow = Vst + (kc * 8 + q) * VLD + g;
#pragma unroll
            for (int df = 0; df < 8; df++) {
                unsigned bbv[2];
                bbv[0] = __float_as_uint(vrow[df * 8]);
                bbv[1] = __float_as_uint(vrow[4 * VLD + df * 8]);
                mma8(oacc[df], pa, bbv);
            }
        }
        __syncthreads();
    }

    // ---- epilogue: quad-reduce row sums, normalize, write [b,m,d] ----
    l0 += __shfl_xor_sync(0xffffffffu, l0, 1);
    l0 += __shfl_xor_sync(0xffffffffu, l0, 2);
    l1 += __shfl_xor_sync(0xffffffffu, l1, 1);
    l1 += __shfl_xor_sync(0xffffffffu, l1, 2);
    float i0 = 1.0f / l0, i1 = 1.0f / l1;
    float* ob = g_ao + (size_t)b * M * DMODEL + (size_t)hh * DHEAD;
#pragma unroll
    for (int df = 0; df < 8; df++) {
        float2 r0 = make_float2(oacc[df][0] * i0, oacc[df][1] * i0);
        float2 r1 = make_float2(oacc[df][2] * i1, oacc[df][3] * i1);
        *(float2*)&ob[(size_t)(mw + g) * DMODEL + df * 8 + 2 * q] = r0;
        *(float2*)&ob[(size_t)(mw + g + 8) * DMODEL + df * 8 + 2 * q] = r1;
    }
}

// ---------------- output projection + mask: raw mma tf32 ----------------
__global__ __launch_bounds__(256) void oproj_gemm(
    const float* __restrict__ Wo, const float* __restrict__ bo,
    float* __restrict__ out)
{
    extern __shared__ float sm[];
    float* Xs[2] = { sm,                 sm + 128 * GLD };
    float* Ws[2] = { sm + 2 * 128 * GLD, sm + 3 * 128 * GLD };

    const int t = threadIdx.x, warp = t >> 5, lane = t & 31;
    const int g = lane >> 2, q = lane & 3;
    const int wm = warp >> 1, wn = warp & 1;
    const int n0 = blockIdx.y << 7, e0 = blockIdx.x << 7;

    const int srow = t >> 3, sc4 = (t & 7) << 2;

    float acc[2][8][4] = {};
    float4 xr[4], wr[4];

    auto ldg = [&](int kk) {
#pragma unroll
        for (int j = 0; j < 4; j++) {
            int row = srow + j * 32;
            xr[j] = *(const float4*)&g_ao[(size_t)(n0 + row) * DMODEL + kk + sc4];
            wr[j] = *(const float4*)&Wo[(size_t)(e0 + row) * DMODEL + kk + sc4];
        }
    };
    auto sts = [&](int buf) {
#pragma unroll
        for (int j = 0; j < 4; j++) {
            int row = srow + j * 32;
            float* xd = Xs[buf] + row * GLD + sc4;
            float* wd = Ws[buf] + row * GLD + sc4;
            float4 xv = xr[j], wv = wr[j];
            xd[0] = __uint_as_float(f2tf(xv.x)); xd[1] = __uint_as_float(f2tf(xv.y));
            xd[2] = __uint_as_float(f2tf(xv.z)); xd[3] = __uint_as_float(f2tf(xv.w));
            wd[0] = __uint_as_float(f2tf(wv.x)); wd[1] = __uint_as_float(f2tf(wv.y));
            wd[2] = __uint_as_float(f2tf(wv.z)); wd[3] = __uint_as_float(f2tf(wv.w));
        }
    };

    ldg(0); sts(0); __syncthreads();
    for (int it = 0; it < 16; it++) {
        if (it < 15) ldg((it + 1) * 32);
        const int buf = it & 1;
#pragma unroll
        for (int kc = 0; kc < 4; kc++) {
            unsigned af[2][4], bf[8][2];
#pragma unroll
            for (int mf = 0; mf < 2; mf++) {
                const float* ap = Xs[buf] + (wm * 32 + mf * 16 + g) * GLD + kc * 8 + q;
                af[mf][0] = __float_as_uint(ap[0]);
                af[mf][1] = __float_as_uint(ap[8 * GLD]);
                af[mf][2] = __float_as_uint(ap[4]);
                af[mf][3] = __float_as_uint(ap[8 * GLD + 4]);
            }
#pragma unroll
            for (int nf = 0; nf < 8; nf++) {
                const float* bp = Ws[buf] + (wn * 64 + nf * 8 + g) * GLD + kc * 8 + q;
                bf[nf][0] = __float_as_uint(bp[0]);
                bf[nf][1] = __float_as_uint(bp[4]);
            }
#pragma unroll
            for (int mf = 0; mf < 2; mf++)
#pragma unroll
                for (int nf = 0; nf < 8; nf++) mma8(acc[mf][nf], af[mf], bf[nf]);
        }
        if (it < 15) { sts((it + 1) & 1); __syncthreads(); }
    }

#pragma unroll
    for (int mf = 0; mf < 2; mf++) {
        int ntA = n0 + wm * 32 + mf * 16 + g;
        int ntB = ntA + 8;
        float mkA = (float)g_mask[ntA];
        float mkB = (float)g_mask[ntB];
#pragma unroll
        for (int nf = 0; nf < 8; nf++) {
            int e = e0 + wn * 64 + nf * 8 + 2 * q;
            float b0v = bo[e], b1v = bo[e + 1];
            float2 rA = make_float2((acc[mf][nf][0] + b0v) * mkA,
                                    (acc[mf][nf][1] + b1v) * mkA);
            float2 rB = make_float2((acc[mf][nf][2] + b0v) * mkB,
                                    (acc[mf][nf][3] + b1v) * mkB);
            *(float2*)&out[(size_t)ntA * DMODEL + e] = rA;
            *(float2*)&out[(size_t)ntB * DMODEL + e] = rB;
        }
    }
}

// ---------------- launch ----------------
extern "C" void kernel_launch(void* const* d_in, const int* in_sizes, int n_in,
                              void* d_out, int out_size) {
    const float* h  = (const float*)d_in[0];
    const void*  pm = d_in[1];
    const float* Wq = (const float*)d_in[2];
    const float* bq = (const float*)d_in[3];
    const float* Wk = (const float*)d_in[4];
    const float* bk = (const float*)d_in[5];
    const float* Wv = (const float*)d_in[6];
    const float* bv = (const float*)d_in[7];
    const float* Wo = (const float*)d_in[8];
    const float* bo = (const float*)d_in[9];
    float* out = (float*)d_out;

    mask_convert<<<1, 256>>>((const unsigned int*)pm, NTOK);
    bias_init<<<8, 256>>>();

    cudaFuncSetAttribute(qkv_gemm, cudaFuncAttributeMaxDynamicSharedMemorySize, GEMM_SMEM);
    cudaFuncSetAttribute(oproj_gemm, cudaFuncAttributeMaxDynamicSharedMemorySize, GEMM_SMEM);
    cudaFuncSetAttribute(attn_kernel, cudaFuncAttributeMaxDynamicSharedMemorySize, ATT_SMEM);

    dim3 g1(DMODEL / 128, NTOK / 128, 3);
    qkv_gemm<<<g1, 256, GEMM_SMEM>>>(h, Wq, bq, Wk, bk, Wv, bv);

    dim3 g2(M / 128, BH);
    attn_kernel<<<g2, 256, ATT_SMEM>>>();

    dim3 g3(DMODEL / 128, NTOK / 128);
    oproj_gemm<<<g3, 256, GEMM_SMEM>>>(Wo, bo, out);
}

// round 6
// speedup vs baseline: 3.0614x; 1.0888x over previous
#include <cuda_runtime.h>
#include <math.h>

#define B 4
#define M 2048
#define DMODEL 512
#define NHEAD 8
#define DHEAD 64
#define NTOK (B*M)          // 8192
#define BH (B*NHEAD)        // 32

// ---------------- scratch (device globals) ----------------
__device__ float g_q[BH * M * DHEAD];    // [b,h,m,dh], tf32-rounded, pre-scaled 1/8
__device__ float g_k[BH * M * DHEAD];    // [b,h,m,dh] tf32-rounded
__device__ float g_v[BH * DHEAD * M];    // [b,h,dh,m] TRANSPOSED, tf32-rounded
__device__ float g_ao[NTOK * DMODEL];    // attention output, [b,m,d] fp32
__device__ float g_bias[M];              // log(exp(-d)+1e-12)
__device__ int   g_mask[NTOK];
__device__ unsigned g_mbits[NTOK / 32];  // packed mask bits

// ---------------- ptx helpers ----------------
__device__ __forceinline__ unsigned smem_u32(const void* p) {
    return (unsigned)__cvta_generic_to_shared(p);
}
__device__ __forceinline__ void cp16(unsigned d, const void* s) {
    asm volatile("cp.async.cg.shared.global [%0],[%1],16;\n" :: "r"(d), "l"(s) : "memory");
}
__device__ __forceinline__ void cp_commit() {
    asm volatile("cp.async.commit_group;\n" ::: "memory");
}
template<int N> __device__ __forceinline__ void cp_wait() {
    asm volatile("cp.async.wait_group %0;\n" :: "n"(N) : "memory");
}
__device__ __forceinline__ unsigned f2tf(float f) {
    unsigned u; asm("cvt.rna.tf32.f32 %0,%1;" : "=r"(u) : "f"(f)); return u;
}
__device__ __forceinline__ void mma8(float* c, const unsigned* a, const unsigned* b) {
    asm volatile(
        "mma.sync.aligned.m16n8k8.row.col.f32.tf32.tf32.f32 "
        "{%0,%1,%2,%3},{%4,%5,%6,%7},{%8,%9},{%0,%1,%2,%3};\n"
        : "+f"(c[0]), "+f"(c[1]), "+f"(c[2]), "+f"(c[3])
        : "r"(a[0]), "r"(a[1]), "r"(a[2]), "r"(a[3]), "r"(b[0]), "r"(b[1]));
}
__device__ __forceinline__ void ldsm4(unsigned& r0, unsigned& r1, unsigned& r2, unsigned& r3,
                                      unsigned addr) {
    asm volatile("ldmatrix.sync.aligned.m8n8.x4.shared.b16 {%0,%1,%2,%3},[%4];\n"
                 : "=r"(r0), "=r"(r1), "=r"(r2), "=r"(r3) : "r"(addr));
}

// ---------------- mask dtype sniff + convert + bit-pack ----------------
__global__ void mask_convert(const unsigned int* __restrict__ w, int n) {
    __shared__ int not01, not0f;
    if (threadIdx.x == 0) { not01 = 0; not0f = 0; }
    __syncthreads();
    int b01 = 0, b0f = 0;
    for (int i = threadIdx.x; i < 2048; i += blockDim.x) {
        unsigned v = w[i];
        if (v > 1u) b01 = 1;
        if (v != 0u && v != 0x3F800000u) b0f = 1;
    }
    if (b01) atomicOr(&not01, 1);
    if (b0f) atomicOr(&not0f, 1);
    __syncthreads();
    int mode = (!not01) ? 1 : ((!not0f) ? 2 : 0); // 1=int32, 2=float32, 0=uint8
    for (int i = threadIdx.x; i < n; i += blockDim.x) {
        int v;
        if (mode == 1)      v = (((const int*)w)[i] != 0);
        else if (mode == 2) v = (((const float*)w)[i] != 0.0f);
        else                v = (((const unsigned char*)w)[i] != 0);
        g_mask[i] = v;
    }
    __syncthreads();
    for (int wi = threadIdx.x; wi < n / 32; wi += blockDim.x) {
        unsigned bits = 0;
        for (int k = 0; k < 32; k++) bits |= (g_mask[wi * 32 + k] ? 1u : 0u) << k;
        g_mbits[wi] = bits;
    }
}

__global__ void bias_init() {
    int i = blockIdx.x * blockDim.x + threadIdx.x;
    if (i < M) g_bias[i] = logf(expf(-(float)i) + 1e-12f);
}

// ---------------- QKV projection: raw mma tf32, 128x128 C tile ----------------
#define GLD 36
#define GEMM_SMEM (4 * 128 * GLD * 4)   // 73728

__global__ __launch_bounds__(256, 2) void qkv_gemm(
    const float* __restrict__ X,
    const float* __restrict__ Wq, const float* __restrict__ bq,
    const float* __restrict__ Wk, const float* __restrict__ bk,
    const float* __restrict__ Wv, const float* __restrict__ bv)
{
    extern __shared__ float sm[];
    float* Xs[2] = { sm,                 sm + 128 * GLD };
    float* Ws[2] = { sm + 2 * 128 * GLD, sm + 3 * 128 * GLD };

    const int z = blockIdx.z;
    const float* W    = (z == 0) ? Wq : (z == 1) ? Wk : Wv;
    const float* bias = (z == 0) ? bq : (z == 1) ? bk : bv;
    float* out        = (z == 0) ? g_q : (z == 1) ? g_k : g_v;
    const float oscale = (z == 0) ? 0.125f : 1.0f;

    const int t = threadIdx.x, warp = t >> 5, lane = t & 31;
    const int g = lane >> 2, q = lane & 3;
    const int wm = warp >> 1, wn = warp & 1;
    const int n0 = blockIdx.y << 7, e0 = blockIdx.x << 7;

    const int srow = t >> 3, sc4 = (t & 7) << 2;

    float acc[2][8][4] = {};
    float4 xr[4], wr[4];

    auto ldg = [&](int kk) {
#pragma unroll
        for (int j = 0; j < 4; j++) {
            int row = srow + j * 32;
            xr[j] = *(const float4*)&X[(size_t)(n0 + row) * DMODEL + kk + sc4];
            wr[j] = *(const float4*)&W[(size_t)(e0 + row) * DMODEL + kk + sc4];
        }
    };
    auto sts = [&](int buf) {
#pragma unroll
        for (int j = 0; j < 4; j++) {
            int row = srow + j * 32;
            float* xd = Xs[buf] + row * GLD + sc4;
            float* wd = Ws[buf] + row * GLD + sc4;
            float4 xv = xr[j], wv = wr[j];
            xd[0] = __uint_as_float(f2tf(xv.x)); xd[1] = __uint_as_float(f2tf(xv.y));
            xd[2] = __uint_as_float(f2tf(xv.z)); xd[3] = __uint_as_float(f2tf(xv.w));
            wd[0] = __uint_as_float(f2tf(wv.x)); wd[1] = __uint_as_float(f2tf(wv.y));
            wd[2] = __uint_as_float(f2tf(wv.z)); wd[3] = __uint_as_float(f2tf(wv.w));
        }
    };

    ldg(0); sts(0); __syncthreads();
    for (int it = 0; it < 16; it++) {
        if (it < 15) ldg((it + 1) * 32);
        const int buf = it & 1;
#pragma unroll
        for (int kc = 0; kc < 4; kc++) {
            unsigned af[2][4], bf[8][2];
#pragma unroll
            for (int mf = 0; mf < 2; mf++) {
                const float* ap = Xs[buf] + (wm * 32 + mf * 16 + g) * GLD + kc * 8 + q;
                af[mf][0] = __float_as_uint(ap[0]);
                af[mf][1] = __float_as_uint(ap[8 * GLD]);
                af[mf][2] = __float_as_uint(ap[4]);
                af[mf][3] = __float_as_uint(ap[8 * GLD + 4]);
            }
#pragma unroll
            for (int nf = 0; nf < 8; nf++) {
                const float* bp = Ws[buf] + (wn * 64 + nf * 8 + g) * GLD + kc * 8 + q;
                bf[nf][0] = __float_as_uint(bp[0]);
                bf[nf][1] = __float_as_uint(bp[4]);
            }
#pragma unroll
            for (int mf = 0; mf < 2; mf++)
#pragma unroll
                for (int nf = 0; nf < 8; nf++) mma8(acc[mf][nf], af[mf], bf[nf]);
        }
        if (it < 15) { sts((it + 1) & 1); __syncthreads(); }
    }

    // epilogue
#pragma unroll
    for (int mf = 0; mf < 2; mf++) {
        int ntA = n0 + wm * 32 + mf * 16 + g;
        int ntB = ntA + 8;
#pragma unroll
        for (int nf = 0; nf < 8; nf++) {
            int e = e0 + wn * 64 + nf * 8 + 2 * q;
            int hh = e >> 6, dh = e & 63;
            float b0v = bias[e], b1v = bias[e + 1];
            float vA0 = __uint_as_float(f2tf((acc[mf][nf][0] + b0v) * oscale));
            float vA1 = __uint_as_float(f2tf((acc[mf][nf][1] + b1v) * oscale));
            float vB0 = __uint_as_float(f2tf((acc[mf][nf][2] + b0v) * oscale));
            float vB1 = __uint_as_float(f2tf((acc[mf][nf][3] + b1v) * oscale));
            int bA = ntA >> 11, mA = ntA & 2047;
            int bB = ntB >> 11, mB = ntB & 2047;
            if (z == 2) {
                // transposed: g_v[(b*8+hh)*DHEAD + dh][m]
                size_t baseA = ((size_t)bA * 8 + hh) * DHEAD;
                size_t baseB = ((size_t)bB * 8 + hh) * DHEAD;
                out[(baseA + dh) * M + mA]     = vA0;
                out[(baseA + dh + 1) * M + mA] = vA1;
                out[(baseB + dh) * M + mB]     = vB0;
                out[(baseB + dh + 1) * M + mB] = vB1;
            } else {
                *(float2*)&out[(((size_t)bA * 8 + hh) * M + mA) * DHEAD + dh] = make_float2(vA0, vA1);
                *(float2*)&out[(((size_t)bB * 8 + hh) * M + mB) * DHEAD + dh] = make_float2(vB0, vB1);
            }
        }
    }
}

// ---------------- attention: ldmatrix + raw mma tf32, 512 threads ----------------
#define KLD 68
#define VLD 68
#define PLD 68
#define NW 16
// smem floats: K 2*64*68, V 2*64*68, P 16*16*68, bias 2048, mbits 64
#define ATT_SMEM ((2*64*KLD + 2*64*VLD + NW*16*PLD + 2048 + 64) * 4)   // 147712

__global__ __launch_bounds__(512) void attn_kernel() {
    extern __shared__ float sm[];
    float* Ks0    = sm;                                   // [2][64][KLD]
    float* Vt0    = sm + 2 * 64 * KLD;                    // [2][64][VLD], row=d, col=key
    float* Pw_all = sm + 2 * 64 * KLD + 2 * 64 * VLD;     // [NW][16][PLD]
    float* sbias  = Pw_all + NW * 16 * PLD;               // [2048]
    unsigned* mbw = (unsigned*)(sbias + 2048);            // [64]

    const int t = threadIdx.x, warp = t >> 5, lane = t & 31;
    const int g = lane >> 2, q = lane & 3;
    const int bh = blockIdx.y, b = bh >> 3, hh = bh & 7;
    const int m0 = blockIdx.x << 8;                        // 256-row Q tile
    const float* qb = g_q + (size_t)bh * M * DHEAD;
    const float* kb = g_k + (size_t)bh * M * DHEAD;
    const float* vbT = g_v + (size_t)bh * DHEAD * M;       // [dh][m]

    for (int i = t; i < 2048; i += 512) sbias[i] = g_bias[i];
    if (t < 64) mbw[t] = g_mbits[b * 64 + t];

    // Q fragments, resident
    const int mw = m0 + warp * 16;
    unsigned qf[8][4];
    {
        const float* q0 = qb + (size_t)(mw + g) * DHEAD;
        const float* q1 = qb + (size_t)(mw + g + 8) * DHEAD;
#pragma unroll
        for (int kc = 0; kc < 8; kc++) {
            qf[kc][0] = __float_as_uint(q0[kc * 8 + q]);
            qf[kc][1] = __float_as_uint(q1[kc * 8 + q]);
            qf[kc][2] = __float_as_uint(q0[kc * 8 + q + 4]);
            qf[kc][3] = __float_as_uint(q1[kc * 8 + q + 4]);
        }
    }

    float oacc[8][4] = {};
    float l0 = 0.0f, l1 = 0.0f;

    // ldmatrix per-lane base offsets (bytes)
    const int brow  = ((lane >> 4) << 3) + (lane & 7);     // B-frag: 0..15 row within pair
    const int bcol4 = ((lane >> 3) & 1) << 2;              // 0 or 4
    const unsigned kfb = (unsigned)((brow * KLD + bcol4) * 4);
    const unsigned vfb = (unsigned)((brow * VLD + bcol4) * 4);
    const int prow  = ((lane >> 3) & 1) * 8 + (lane & 7);  // A-frag rows
    const int pcol4 = (lane >> 4) << 2;
    float* Pw = Pw_all + warp * 16 * PLD;
    const unsigned pa_base = smem_u32(Pw) + (unsigned)((prow * PLD + pcol4) * 4);
    const unsigned ks_base = smem_u32(Ks0);
    const unsigned vs_base = smem_u32(Vt0);

    auto stage = [&](int tile, int buf) {
        const float* ksrc = kb + (size_t)(tile * 64) * DHEAD;
        const float* vsrc = vbT + tile * 64;
        float* kd = Ks0 + buf * 64 * KLD;
        float* vd = Vt0 + buf * 64 * VLD;
#pragma unroll
        for (int j = 0; j < 2; j++) {
            int ck = t + j * 512;                  // 0..1023
            int row = ck >> 4, c16 = ck & 15;
            cp16(smem_u32(kd + row * KLD) + c16 * 16, ksrc + row * 64 + c16 * 4);
            cp16(smem_u32(vd + row * VLD) + c16 * 16, vsrc + (size_t)row * M + c16 * 4);
        }
    };

    stage(0, 0); cp_commit();

    for (int tile = 0; tile < 32; tile++) {
        if (tile < 31) { stage(tile + 1, (tile + 1) & 1); cp_commit(); cp_wait<1>(); }
        else cp_wait<0>();
        __syncthreads();

        const unsigned kbuf = ks_base + (tile & 1) * (64 * KLD * 4) + kfb;
        const unsigned vbuf = vs_base + (tile & 1) * (64 * VLD * 4) + vfb;

        // ---- S = Q K^T ----
        float sacc[8][4] = {};
#pragma unroll
        for (int kc = 0; kc < 8; kc++) {
            unsigned bb[8][2];
#pragma unroll
            for (int np = 0; np < 4; np++) {
                unsigned r0, r1, r2, r3;
                ldsm4(r0, r1, r2, r3, kbuf + np * (16 * KLD * 4) + kc * 32);
                bb[2 * np][0] = r0; bb[2 * np][1] = r1;
                bb[2 * np + 1][0] = r2; bb[2 * np + 1][1] = r3;
            }
#pragma unroll
            for (int nf = 0; nf < 8; nf++) mma8(sacc[nf], qf[kc], bb[nf]);
        }

        // ---- softmax (static max): P = mask ? exp(S + bias) : 0 ----
        const unsigned w0 = mbw[tile * 2], w1 = mbw[tile * 2 + 1];
        const int mg0 = mw + g, mg1 = mw + g + 8;
        const int nbase = tile * 64;
#pragma unroll
        for (int nf = 0; nf < 8; nf++) {
            int off = nf * 8 + 2 * q;
            unsigned wsel = (nf < 4) ? w0 : w1;
            int sh = off & 31;
            bool v0m = (wsel >> sh) & 1;
            bool v1m = (wsel >> (sh + 1)) & 1;
            int n_ = nbase + off;
            int d00 = abs(mg0 - n_), d01 = abs(mg0 - n_ - 1);
            int d10 = abs(mg1 - n_), d11 = abs(mg1 - n_ - 1);
            float p0 = v0m ? __expf(sacc[nf][0] + sbias[d00]) : 0.0f;
            float p1 = v1m ? __expf(sacc[nf][1] + sbias[d01]) : 0.0f;
            float p2 = v0m ? __expf(sacc[nf][2] + sbias[d10]) : 0.0f;
            float p3 = v1m ? __expf(sacc[nf][3] + sbias[d11]) : 0.0f;
            p0 = __uint_as_float(f2tf(p0)); p1 = __uint_as_float(f2tf(p1));
            p2 = __uint_as_float(f2tf(p2)); p3 = __uint_as_float(f2tf(p3));
            l0 += p0 + p1; l1 += p2 + p3;
            *(float2*)&Pw[g * PLD + off]       = make_float2(p0, p1);
            *(float2*)&Pw[(g + 8) * PLD + off] = make_float2(p2, p3);
        }
        __syncwarp();

        // ---- O += P V ----
#pragma unroll
        for (int kc = 0; kc < 8; kc++) {
            unsigned pa[4];
            ldsm4(pa[0], pa[1], pa[2], pa[3], pa_base + kc * 32);
            unsigned vv[8][2];
#pragma unroll
            for (int dp = 0; dp < 4; dp++) {
                unsigned r0, r1, r2, r3;
                ldsm4(r0, r1, r2, r3, vbuf + dp * (16 * VLD * 4) + kc * 32);
                vv[2 * dp][0] = r0; vv[2 * dp][1] = r1;
                vv[2 * dp + 1][0] = r2; vv[2 * dp + 1][1] = r3;
            }
#pragma unroll
            for (int df = 0; df < 8; df++) mma8(oacc[df], pa, vv[df]);
        }
        __syncthreads();
    }

    // ---- epilogue ----
    l0 += __shfl_xor_sync(0xffffffffu, l0, 1);
    l0 += __shfl_xor_sync(0xffffffffu, l0, 2);
    l1 += __shfl_xor_sync(0xffffffffu, l1, 1);
    l1 += __shfl_xor_sync(0xffffffffu, l1, 2);
    float i0 = 1.0f / l0, i1 = 1.0f / l1;
    float* ob = g_ao + (size_t)b * M * DMODEL + (size_t)hh * DHEAD;
#pragma unroll
    for (int df = 0; df < 8; df++) {
        float2 r0 = make_float2(oacc[df][0] * i0, oacc[df][1] * i0);
        float2 r1 = make_float2(oacc[df][2] * i1, oacc[df][3] * i1);
        *(float2*)&ob[(size_t)(mw + g) * DMODEL + df * 8 + 2 * q] = r0;
        *(float2*)&ob[(size_t)(mw + g + 8) * DMODEL + df * 8 + 2 * q] = r1;
    }
}

// ---------------- output projection + mask: raw mma tf32 ----------------
__global__ __launch_bounds__(256, 2) void oproj_gemm(
    const float* __restrict__ Wo, const float* __restrict__ bo,
    float* __restrict__ out)
{
    extern __shared__ float sm[];
    float* Xs[2] = { sm,                 sm + 128 * GLD };
    float* Ws[2] = { sm + 2 * 128 * GLD, sm + 3 * 128 * GLD };

    const int t = threadIdx.x, warp = t >> 5, lane = t & 31;
    const int g = lane >> 2, q = lane & 3;
    const int wm = warp >> 1, wn = warp & 1;
    const int n0 = blockIdx.y << 7, e0 = blockIdx.x << 7;

    const int srow = t >> 3, sc4 = (t & 7) << 2;

    float acc[2][8][4] = {};
    float4 xr[4], wr[4];

    auto ldg = [&](int kk) {
#pragma unroll
        for (int j = 0; j < 4; j++) {
            int row = srow + j * 32;
            xr[j] = *(const float4*)&g_ao[(size_t)(n0 + row) * DMODEL + kk + sc4];
            wr[j] = *(const float4*)&Wo[(size_t)(e0 + row) * DMODEL + kk + sc4];
        }
    };
    auto sts = [&](int buf) {
#pragma unroll
        for (int j = 0; j < 4; j++) {
            int row = srow + j * 32;
            float* xd = Xs[buf] + row * GLD + sc4;
            float* wd = Ws[buf] + row * GLD + sc4;
            float4 xv = xr[j], wv = wr[j];
            xd[0] = __uint_as_float(f2tf(xv.x)); xd[1] = __uint_as_float(f2tf(xv.y));
            xd[2] = __uint_as_float(f2tf(xv.z)); xd[3] = __uint_as_float(f2tf(xv.w));
            wd[0] = __uint_as_float(f2tf(wv.x)); wd[1] = __uint_as_float(f2tf(wv.y));
            wd[2] = __uint_as_float(f2tf(wv.z)); wd[3] = __uint_as_float(f2tf(wv.w));
        }
    };

    ldg(0); sts(0); __syncthreads();
    for (int it = 0; it < 16; it++) {
        if (it < 15) ldg((it + 1) * 32);
        const int buf = it & 1;
#pragma unroll
        for (int kc = 0; kc < 4; kc++) {
            unsigned af[2][4], bf[8][2];
#pragma unroll
            for (int mf = 0; mf < 2; mf++) {
                const float* ap = Xs[buf] + (wm * 32 + mf * 16 + g) * GLD + kc * 8 + q;
                af[mf][0] = __float_as_uint(ap[0]);
                af[mf][1] = __float_as_uint(ap[8 * GLD]);
                af[mf][2] = __float_as_uint(ap[4]);
                af[mf][3] = __float_as_uint(ap[8 * GLD + 4]);
            }
#pragma unroll
            for (int nf = 0; nf < 8; nf++) {
                const float* bp = Ws[buf] + (wn * 64 + nf * 8 + g) * GLD + kc * 8 + q;
                bf[nf][0] = __float_as_uint(bp[0]);
                bf[nf][1] = __float_as_uint(bp[4]);
            }
#pragma unroll
            for (int mf = 0; mf < 2; mf++)
#pragma unroll
                for (int nf = 0; nf < 8; nf++) mma8(acc[mf][nf], af[mf], bf[nf]);
        }
        if (it < 15) { sts((it + 1) & 1); __syncthreads(); }
    }

#pragma unroll
    for (int mf = 0; mf < 2; mf++) {
        int ntA = n0 + wm * 32 + mf * 16 + g;
        int ntB = ntA + 8;
        float mkA = (float)g_mask[ntA];
        float mkB = (float)g_mask[ntB];
#pragma unroll
        for (int nf = 0; nf < 8; nf++) {
            int e = e0 + wn * 64 + nf * 8 + 2 * q;
            float b0v = bo[e], b1v = bo[e + 1];
            float2 rA = make_float2((acc[mf][nf][0] + b0v) * mkA,
                                    (acc[mf][nf][1] + b1v) * mkA);
            float2 rB = make_float2((acc[mf][nf][2] + b0v) * mkB,
                                    (acc[mf][nf][3] + b1v) * mkB);
            *(float2*)&out[(size_t)ntA * DMODEL + e] = rA;
            *(float2*)&out[(size_t)ntB * DMODEL + e] = rB;
        }
    }
}

// ---------------- launch ----------------
extern "C" void kernel_launch(void* const* d_in, const int* in_sizes, int n_in,
                              void* d_out, int out_size) {
    const float* h  = (const float*)d_in[0];
    const void*  pm = d_in[1];
    const float* Wq = (const float*)d_in[2];
    const float* bq = (const float*)d_in[3];
    const float* Wk = (const float*)d_in[4];
    const float* bk = (const float*)d_in[5];
    const float* Wv = (const float*)d_in[6];
    const float* bv = (const float*)d_in[7];
    const float* Wo = (const float*)d_in[8];
    const float* bo = (const float*)d_in[9];
    float* out = (float*)d_out;

    mask_convert<<<1, 256>>>((const unsigned int*)pm, NTOK);
    bias_init<<<8, 256>>>();

    cudaFuncSetAttribute(qkv_gemm, cudaFuncAttributeMaxDynamicSharedMemorySize, GEMM_SMEM);
    cudaFuncSetAttribute(oproj_gemm, cudaFuncAttributeMaxDynamicSharedMemorySize, GEMM_SMEM);
    cudaFuncSetAttribute(attn_kernel, cudaFuncAttributeMaxDynamicSharedMemorySize, ATT_SMEM);

    dim3 g1(DMODEL / 128, NTOK / 128, 3);
    qkv_gemm<<<g1, 256, GEMM_SMEM>>>(h, Wq, bq, Wk, bk, Wv, bv);

    dim3 g2(M / 256, BH);
    attn_kernel<<<g2, 512, ATT_SMEM>>>();

    dim3 g3(DMODEL / 128, NTOK / 128);
    oproj_gemm<<<g3, 256, GEMM_SMEM>>>(Wo, bo, out);
}

// round 7
// speedup vs baseline: 6.2082x; 2.0279x over previous
#include <cuda_runtime.h>
#include <math.h>

#define B 4
#define M 2048
#define DMODEL 512
#define NHEAD 8
#define DHEAD 64
#define NTOK (B*M)          // 8192
#define BH (B*NHEAD)        // 32

// ---------------- scratch (device globals) ----------------
__device__ float g_q[BH * M * DHEAD];    // [b,h,m,dh], tf32-rounded, pre-scaled 1/8
__device__ float g_k[BH * M * DHEAD];    // [b,h,m,dh] tf32-rounded
__device__ float g_v[BH * DHEAD * M];    // [b,h,dh,m] TRANSPOSED, tf32-rounded
__device__ float g_ao[NTOK * DMODEL];    // attention output, [b,m,d] fp32
__device__ float g_bias[M];              // log(exp(-d)+1e-12)
__device__ int   g_mask[NTOK];
__device__ unsigned g_mbits[NTOK / 32];  // packed mask bits

// ---------------- ptx helpers ----------------
__device__ __forceinline__ unsigned smem_u32(const void* p) {
    return (unsigned)__cvta_generic_to_shared(p);
}
__device__ __forceinline__ void cp16(unsigned d, const void* s) {
    asm volatile("cp.async.cg.shared.global [%0],[%1],16;\n" :: "r"(d), "l"(s) : "memory");
}
__device__ __forceinline__ void cp_commit() {
    asm volatile("cp.async.commit_group;\n" ::: "memory");
}
template<int N> __device__ __forceinline__ void cp_wait() {
    asm volatile("cp.async.wait_group %0;\n" :: "n"(N) : "memory");
}
__device__ __forceinline__ unsigned f2tf(float f) {
    unsigned u; asm("cvt.rna.tf32.f32 %0,%1;" : "=r"(u) : "f"(f)); return u;
}
__device__ __forceinline__ void mma8(float* c, const unsigned* a, const unsigned* b) {
    asm volatile(
        "mma.sync.aligned.m16n8k8.row.col.f32.tf32.tf32.f32 "
        "{%0,%1,%2,%3},{%4,%5,%6,%7},{%8,%9},{%0,%1,%2,%3};\n"
        : "+f"(c[0]), "+f"(c[1]), "+f"(c[2]), "+f"(c[3])
        : "r"(a[0]), "r"(a[1]), "r"(a[2]), "r"(a[3]), "r"(b[0]), "r"(b[1]));
}
__device__ __forceinline__ void ldsm4(unsigned& r0, unsigned& r1, unsigned& r2, unsigned& r3,
                                      unsigned addr) {
    asm volatile("ldmatrix.sync.aligned.m8n8.x4.shared.b16 {%0,%1,%2,%3},[%4];\n"
                 : "=r"(r0), "=r"(r1), "=r"(r2), "=r"(r3) : "r"(addr));
}

// ---------------- mask dtype sniff + convert + bit-pack ----------------
__global__ void mask_convert(const unsigned int* __restrict__ w, int n) {
    __shared__ int not01, not0f;
    if (threadIdx.x == 0) { not01 = 0; not0f = 0; }
    __syncthreads();
    int b01 = 0, b0f = 0;
    for (int i = threadIdx.x; i < 2048; i += blockDim.x) {
        unsigned v = w[i];
        if (v > 1u) b01 = 1;
        if (v != 0u && v != 0x3F800000u) b0f = 1;
    }
    if (b01) atomicOr(&not01, 1);
    if (b0f) atomicOr(&not0f, 1);
    __syncthreads();
    int mode = (!not01) ? 1 : ((!not0f) ? 2 : 0); // 1=int32, 2=float32, 0=uint8
    for (int i = threadIdx.x; i < n; i += blockDim.x) {
        int v;
        if (mode == 1)      v = (((const int*)w)[i] != 0);
        else if (mode == 2) v = (((const float*)w)[i] != 0.0f);
        else                v = (((const unsigned char*)w)[i] != 0);
        g_mask[i] = v;
    }
    __syncthreads();
    for (int wi = threadIdx.x; wi < n / 32; wi += blockDim.x) {
        unsigned bits = 0;
        for (int k = 0; k < 32; k++) bits |= (g_mask[wi * 32 + k] ? 1u : 0u) << k;
        g_mbits[wi] = bits;
    }
}

__global__ void bias_init() {
    int i = blockIdx.x * blockDim.x + threadIdx.x;
    if (i < M) g_bias[i] = logf(expf(-(float)i) + 1e-12f);
}

// ---------------- QKV projection: raw mma tf32 + ldmatrix, 128x128 tile ----------------
#define GLD 36
#define GEMM_SMEM (4 * 128 * GLD * 4)   // 73728

__global__ __launch_bounds__(256, 2) void qkv_gemm(
    const float* __restrict__ X,
    const float* __restrict__ Wq, const float* __restrict__ bq,
    const float* __restrict__ Wk, const float* __restrict__ bk,
    const float* __restrict__ Wv, const float* __restrict__ bv)
{
    extern __shared__ float sm[];
    float* Xs[2] = { sm,                 sm + 128 * GLD };
    float* Ws[2] = { sm + 2 * 128 * GLD, sm + 3 * 128 * GLD };

    const int z = blockIdx.z;
    const float* W    = (z == 0) ? Wq : (z == 1) ? Wk : Wv;
    const float* bias = (z == 0) ? bq : (z == 1) ? bk : bv;
    float* out        = (z == 0) ? g_q : (z == 1) ? g_k : g_v;
    const float oscale = (z == 0) ? 0.125f : 1.0f;

    const int t = threadIdx.x, warp = t >> 5, lane = t & 31;
    const int q = lane & 3;
    const int wm = warp >> 1, wn = warp & 1;
    const int n0 = blockIdx.y << 7, e0 = blockIdx.x << 7;

    const int srow = t >> 3, sc4 = (t & 7) << 2;

    // ldmatrix lane offsets (element units)
    const int arow  = (lane & 7) + ((lane >> 3) & 1) * 8;
    const int acol4 = (lane >> 4) << 2;
    const int brow  = ((lane >> 4) << 3) + (lane & 7);
    const int bcol4 = ((lane >> 3) & 1) << 2;

    float acc[2][8][4] = {};
    float4 xr[4], wr[4];

    auto ldg = [&](int kk) {
#pragma unroll
        for (int j = 0; j < 4; j++) {
            int row = srow + j * 32;
            xr[j] = *(const float4*)&X[(size_t)(n0 + row) * DMODEL + kk + sc4];
            wr[j] = *(const float4*)&W[(size_t)(e0 + row) * DMODEL + kk + sc4];
        }
    };
    auto sts = [&](int buf) {
#pragma unroll
        for (int j = 0; j < 4; j++) {
            int row = srow + j * 32;
            float* xd = Xs[buf] + row * GLD + sc4;
            float* wd = Ws[buf] + row * GLD + sc4;
            float4 xv = xr[j], wv = wr[j];
            xd[0] = __uint_as_float(f2tf(xv.x)); xd[1] = __uint_as_float(f2tf(xv.y));
            xd[2] = __uint_as_float(f2tf(xv.z)); xd[3] = __uint_as_float(f2tf(xv.w));
            wd[0] = __uint_as_float(f2tf(wv.x)); wd[1] = __uint_as_float(f2tf(wv.y));
            wd[2] = __uint_as_float(f2tf(wv.z)); wd[3] = __uint_as_float(f2tf(wv.w));
        }
    };

    ldg(0); sts(0); __syncthreads();
    for (int it = 0; it < 16; it++) {
        if (it < 15) ldg((it + 1) * 32);
        const int buf = it & 1;
        const unsigned xa = smem_u32(Xs[buf]) + (unsigned)(((wm * 32 + arow) * GLD + acol4) * 4);
        const unsigned wa = smem_u32(Ws[buf]) + (unsigned)(((wn * 64 + brow) * GLD + bcol4) * 4);
#pragma unroll
        for (int kc = 0; kc < 4; kc++) {
            unsigned af[2][4], bf[8][2];
#pragma unroll
            for (int mf = 0; mf < 2; mf++)
                ldsm4(af[mf][0], af[mf][1], af[mf][2], af[mf][3],
                      xa + (unsigned)((mf * 16 * GLD + kc * 8) * 4));
#pragma unroll
            for (int np = 0; np < 4; np++) {
                unsigned r0, r1, r2, r3;
                ldsm4(r0, r1, r2, r3, wa + (unsigned)((np * 16 * GLD + kc * 8) * 4));
                bf[2 * np][0] = r0;     bf[2 * np][1] = r1;
                bf[2 * np + 1][0] = r2; bf[2 * np + 1][1] = r3;
            }
#pragma unroll
            for (int mf = 0; mf < 2; mf++)
#pragma unroll
                for (int nf = 0; nf < 8; nf++) mma8(acc[mf][nf], af[mf], bf[nf]);
        }
        if (it < 15) { sts((it + 1) & 1); __syncthreads(); }
    }

    // epilogue
    const int g = lane >> 2;
#pragma unroll
    for (int mf = 0; mf < 2; mf++) {
        int ntA = n0 + wm * 32 + mf * 16 + g;
        int ntB = ntA + 8;
#pragma unroll
        for (int nf = 0; nf < 8; nf++) {
            int e = e0 + wn * 64 + nf * 8 + 2 * q;
            int hh = e >> 6, dh = e & 63;
            float b0v = bias[e], b1v = bias[e + 1];
            float vA0 = __uint_as_float(f2tf((acc[mf][nf][0] + b0v) * oscale));
            float vA1 = __uint_as_float(f2tf((acc[mf][nf][1] + b1v) * oscale));
            float vB0 = __uint_as_float(f2tf((acc[mf][nf][2] + b0v) * oscale));
            float vB1 = __uint_as_float(f2tf((acc[mf][nf][3] + b1v) * oscale));
            int bA = ntA >> 11, mA = ntA & 2047;
            int bB = ntB >> 11, mB = ntB & 2047;
            if (z == 2) {
                size_t baseA = ((size_t)bA * 8 + hh) * DHEAD;
                size_t baseB = ((size_t)bB * 8 + hh) * DHEAD;
                out[(baseA + dh) * M + mA]     = vA0;
                out[(baseA + dh + 1) * M + mA] = vA1;
                out[(baseB + dh) * M + mB]     = vB0;
                out[(baseB + dh + 1) * M + mB] = vB1;
            } else {
                *(float2*)&out[(((size_t)bA * 8 + hh) * M + mA) * DHEAD + dh] = make_float2(vA0, vA1);
                *(float2*)&out[(((size_t)bB * 8 + hh) * M + mB) * DHEAD + dh] = make_float2(vB0, vB1);
            }
        }
    }
}

// ---------------- attention: banded + ldmatrix + raw mma tf32 ----------------
// 256 threads, 8 warps; Q tile 256 rows, 32 rows/warp; 64-key tiles within +-64 band.
#define KLD 68
#define VLD 68
#define PLD 68
// floats: K 2*64*68 + V 2*64*68 + P 8*32*68 + bias 2048 + mbits 64
#define ATT_SMEM ((2*64*KLD + 2*64*VLD + 8*32*PLD + 2048 + 64) * 4)   // 147712

__global__ __launch_bounds__(256) void attn_kernel() {
    extern __shared__ float sm[];
    float* Ks0    = sm;                                   // [2][64][KLD]
    float* Vt0    = sm + 2 * 64 * KLD;                    // [2][64][VLD], row=d, col=key
    float* Pw_all = sm + 2 * 64 * KLD + 2 * 64 * VLD;     // [8][32][PLD]
    float* sbias  = Pw_all + 8 * 32 * PLD;                // [2048]
    unsigned* mbw = (unsigned*)(sbias + 2048);            // [64]

    const int t = threadIdx.x, warp = t >> 5, lane = t & 31;
    const int g = lane >> 2, q = lane & 3;
    const int bh = blockIdx.y, b = bh >> 3, hh = bh & 7;
    const int m0 = blockIdx.x << 8;                        // 256-row Q tile
    const float* qb = g_q + (size_t)bh * M * DHEAD;
    const float* kb = g_k + (size_t)bh * M * DHEAD;
    const float* vbT = g_v + (size_t)bh * DHEAD * M;

    for (int i = t; i < 2048; i += 256) sbias[i] = g_bias[i];
    if (t < 64) mbw[t] = g_mbits[b * 64 + t];

    // Q fragments, resident: 32 rows per warp = 2 m-blocks
    const int mw = m0 + warp * 32;
    unsigned qf[2][8][4];
#pragma unroll
    for (int mb = 0; mb < 2; mb++) {
        const float* q0 = qb + (size_t)(mw + mb * 16 + g) * DHEAD;
        const float* q1 = qb + (size_t)(mw + mb * 16 + g + 8) * DHEAD;
#pragma unroll
        for (int kc = 0; kc < 8; kc++) {
            qf[mb][kc][0] = __float_as_uint(q0[kc * 8 + q]);
            qf[mb][kc][1] = __float_as_uint(q1[kc * 8 + q]);
            qf[mb][kc][2] = __float_as_uint(q0[kc * 8 + q + 4]);
            qf[mb][kc][3] = __float_as_uint(q1[kc * 8 + q + 4]);
        }
    }

    float oacc[2][8][4] = {};
    float lr[2][2] = {};

    const int brow  = ((lane >> 4) << 3) + (lane & 7);
    const int bcol4 = ((lane >> 3) & 1) << 2;
    const unsigned kfb = (unsigned)((brow * KLD + bcol4) * 4);
    const unsigned vfb = (unsigned)((brow * VLD + bcol4) * 4);
    const int prow  = (lane & 7) + ((lane >> 3) & 1) * 8;
    const int pcol4 = (lane >> 4) << 2;
    float* Pw = Pw_all + warp * 32 * PLD;
    const unsigned pa_base = smem_u32(Pw) + (unsigned)((prow * PLD + pcol4) * 4);
    const unsigned ks_base = smem_u32(Ks0);
    const unsigned vs_base = smem_u32(Vt0);

    auto stage = [&](int tile, int buf) {
        const float* ksrc = kb + (size_t)(tile * 64) * DHEAD;
        const float* vsrc = vbT + tile * 64;
        float* kd = Ks0 + buf * 64 * KLD;
        float* vd = Vt0 + buf * 64 * VLD;
#pragma unroll
        for (int j = 0; j < 4; j++) {
            int ck = t + j * 256;                  // 0..1023
            int row = ck >> 4, c16 = ck & 15;
            cp16(smem_u32(kd + row * KLD) + c16 * 16, ksrc + row * 64 + c16 * 4);
            cp16(smem_u32(vd + row * VLD) + c16 * 16, vsrc + (size_t)row * M + c16 * 4);
        }
    };

    // banded tile range: keys within +-64 of [m0, m0+255]
    const int tlo = max(0, (m0 >> 6) - 1);
    const int thi = min(M / 64 - 1, (m0 >> 6) + 4);

    stage(tlo, 0); cp_commit();

    for (int tile = tlo; tile <= thi; tile++) {
        const int bufi = (tile - tlo) & 1;
        if (tile < thi) { stage(tile + 1, bufi ^ 1); cp_commit(); cp_wait<1>(); }
        else cp_wait<0>();
        __syncthreads();

        const int n0 = tile << 6;
        // per-warp band check (warp-uniform)
        if (n0 <= mw + 95 && n0 + 63 >= mw - 64) {
            const unsigned kbuf = ks_base + bufi * (64 * KLD * 4) + kfb;
            const unsigned vbuf = vs_base + bufi * (64 * VLD * 4) + vfb;

            // ---- S = Q K^T ----
            float sacc[2][8][4] = {};
#pragma unroll
            for (int kc = 0; kc < 8; kc++) {
                unsigned bb[8][2];
#pragma unroll
                for (int np = 0; np < 4; np++) {
                    unsigned r0, r1, r2, r3;
                    ldsm4(r0, r1, r2, r3, kbuf + np * (16 * KLD * 4) + kc * 32);
                    bb[2 * np][0] = r0;     bb[2 * np][1] = r1;
                    bb[2 * np + 1][0] = r2; bb[2 * np + 1][1] = r3;
                }
#pragma unroll
                for (int mb = 0; mb < 2; mb++)
#pragma unroll
                    for (int nf = 0; nf < 8; nf++) mma8(sacc[mb][nf], qf[mb][kc], bb[nf]);
            }

            // ---- softmax (static max) + P store ----
            const unsigned w0 = mbw[tile * 2], w1 = mbw[tile * 2 + 1];
#pragma unroll
            for (int mb = 0; mb < 2; mb++) {
                const int mg0 = mw + mb * 16 + g, mg1 = mg0 + 8;
#pragma unroll
                for (int nf = 0; nf < 8; nf++) {
                    int off = nf * 8 + 2 * q;
                    unsigned wsel = (nf < 4) ? w0 : w1;
                    int sh = off & 31;
                    bool v0m = (wsel >> sh) & 1;
                    bool v1m = (wsel >> (sh + 1)) & 1;
                    int n_ = n0 + off;
                    int d00 = abs(mg0 - n_), d01 = abs(mg0 - n_ - 1);
                    int d10 = abs(mg1 - n_), d11 = abs(mg1 - n_ - 1);
                    float p0 = v0m ? __expf(sacc[mb][nf][0] + sbias[d00]) : 0.0f;
                    float p1 = v1m ? __expf(sacc[mb][nf][1] + sbias[d01]) : 0.0f;
                    float p2 = v0m ? __expf(sacc[mb][nf][2] + sbias[d10]) : 0.0f;
                    float p3 = v1m ? __expf(sacc[mb][nf][3] + sbias[d11]) : 0.0f;
                    p0 = __uint_as_float(f2tf(p0)); p1 = __uint_as_float(f2tf(p1));
                    p2 = __uint_as_float(f2tf(p2)); p3 = __uint_as_float(f2tf(p3));
                    lr[mb][0] += p0 + p1; lr[mb][1] += p2 + p3;
                    *(float2*)&Pw[(mb * 16 + g) * PLD + off]     = make_float2(p0, p1);
                    *(float2*)&Pw[(mb * 16 + g + 8) * PLD + off] = make_float2(p2, p3);
                }
            }
            __syncwarp();

            // ---- O += P V ----
#pragma unroll
            for (int kc = 0; kc < 8; kc++) {
                unsigned pa[2][4];
#pragma unroll
                for (int mb = 0; mb < 2; mb++)
                    ldsm4(pa[mb][0], pa[mb][1], pa[mb][2], pa[mb][3],
                          pa_base + mb * (16 * PLD * 4) + kc * 32);
                unsigned vv[8][2];
#pragma unroll
                for (int dp = 0; dp < 4; dp++) {
                    unsigned r0, r1, r2, r3;
                    ldsm4(r0, r1, r2, r3, vbuf + dp * (16 * VLD * 4) + kc * 32);
                    vv[2 * dp][0] = r0;     vv[2 * dp][1] = r1;
                    vv[2 * dp + 1][0] = r2; vv[2 * dp + 1][1] = r3;
                }
#pragma unroll
                for (int mb = 0; mb < 2; mb++)
#pragma unroll
                    for (int df = 0; df < 8; df++) mma8(oacc[mb][df], pa[mb], vv[df]);
            }
        }
        __syncthreads();
    }

    // ---- epilogue ----
    float* ob = g_ao + (size_t)b * M * DMODEL + (size_t)hh * DHEAD;
#pragma unroll
    for (int mb = 0; mb < 2; mb++) {
        float l0 = lr[mb][0], l1 = lr[mb][1];
        l0 += __shfl_xor_sync(0xffffffffu, l0, 1);
        l0 += __shfl_xor_sync(0xffffffffu, l0, 2);
        l1 += __shfl_xor_sync(0xffffffffu, l1, 1);
        l1 += __shfl_xor_sync(0xffffffffu, l1, 2);
        float i0 = 1.0f / fmaxf(l0, 1e-30f);
        float i1 = 1.0f / fmaxf(l1, 1e-30f);
        int r0 = mw + mb * 16 + g, r1 = r0 + 8;
#pragma unroll
        for (int df = 0; df < 8; df++) {
            *(float2*)&ob[(size_t)r0 * DMODEL + df * 8 + 2 * q] =
                make_float2(oacc[mb][df][0] * i0, oacc[mb][df][1] * i0);
            *(float2*)&ob[(size_t)r1 * DMODEL + df * 8 + 2 * q] =
                make_float2(oacc[mb][df][2] * i1, oacc[mb][df][3] * i1);
        }
    }
}

// ---------------- output projection + mask: raw mma tf32 + ldmatrix ----------------
__global__ __launch_bounds__(256, 2) void oproj_gemm(
    const float* __restrict__ Wo, const float* __restrict__ bo,
    float* __restrict__ out)
{
    extern __shared__ float sm[];
    float* Xs[2] = { sm,                 sm + 128 * GLD };
    float* Ws[2] = { sm + 2 * 128 * GLD, sm + 3 * 128 * GLD };

    const int t = threadIdx.x, warp = t >> 5, lane = t & 31;
    const int q = lane & 3;
    const int wm = warp >> 1, wn = warp & 1;
    const int n0 = blockIdx.y << 7, e0 = blockIdx.x << 7;

    const int srow = t >> 3, sc4 = (t & 7) << 2;

    const int arow  = (lane & 7) + ((lane >> 3) & 1) * 8;
    const int acol4 = (lane >> 4) << 2;
    const int brow  = ((lane >> 4) << 3) + (lane & 7);
    const int bcol4 = ((lane >> 3) & 1) << 2;

    float acc[2][8][4] = {};
    float4 xr[4], wr[4];

    auto ldg = [&](int kk) {
#pragma unroll
        for (int j = 0; j < 4; j++) {
            int row = srow + j * 32;
            xr[j] = *(const float4*)&g_ao[(size_t)(n0 + row) * DMODEL + kk + sc4];
            wr[j] = *(const float4*)&Wo[(size_t)(e0 + row) * DMODEL + kk + sc4];
        }
    };
    auto sts = [&](int buf) {
#pragma unroll
        for (int j = 0; j < 4; j++) {
            int row = srow + j * 32;
            float* xd = Xs[buf] + row * GLD + sc4;
            float* wd = Ws[buf] + row * GLD + sc4;
            float4 xv = xr[j], wv = wr[j];
            xd[0] = __uint_as_float(f2tf(xv.x)); xd[1] = __uint_as_float(f2tf(xv.y));
            xd[2] = __uint_as_float(f2tf(xv.z)); xd[3] = __uint_as_float(f2tf(xv.w));
            wd[0] = __uint_as_float(f2tf(wv.x)); wd[1] = __uint_as_float(f2tf(wv.y));
            wd[2] = __uint_as_float(f2tf(wv.z)); wd[3] = __uint_as_float(f2tf(wv.w));
        }
    };

    ldg(0); sts(0); __syncthreads();
    for (int it = 0; it < 16; it++) {
        if (it < 15) ldg((it + 1) * 32);
        const int buf = it & 1;
        const unsigned xa = smem_u32(Xs[buf]) + (unsigned)(((wm * 32 + arow) * GLD + acol4) * 4);
        const unsigned wa = smem_u32(Ws[buf]) + (unsigned)(((wn * 64 + brow) * GLD + bcol4) * 4);
#pragma unroll
        for (int kc = 0; kc < 4; kc++) {
            unsigned af[2][4], bf[8][2];
#pragma unroll
            for (int mf = 0; mf < 2; mf++)
                ldsm4(af[mf][0], af[mf][1], af[mf][2], af[mf][3],
                      xa + (unsigned)((mf * 16 * GLD + kc * 8) * 4));
#pragma unroll
            for (int np = 0; np < 4; np++) {
                unsigned r0, r1, r2, r3;
                ldsm4(r0, r1, r2, r3, wa + (unsigned)((np * 16 * GLD + kc * 8) * 4));
                bf[2 * np][0] = r0;     bf[2 * np][1] = r1;
                bf[2 * np + 1][0] = r2; bf[2 * np + 1][1] = r3;
            }
#pragma unroll
            for (int mf = 0; mf < 2; mf++)
#pragma unroll
                for (int nf = 0; nf < 8; nf++) mma8(acc[mf][nf], af[mf], bf[nf]);
        }
        if (it < 15) { sts((it + 1) & 1); __syncthreads(); }
    }

    const int g = lane >> 2;
#pragma unroll
    for (int mf = 0; mf < 2; mf++) {
        int ntA = n0 + wm * 32 + mf * 16 + g;
        int ntB = ntA + 8;
        float mkA = (float)g_mask[ntA];
        float mkB = (float)g_mask[ntB];
#pragma unroll
        for (int nf = 0; nf < 8; nf++) {
            int e = e0 + wn * 64 + nf * 8 + 2 * q;
            float b0v = bo[e], b1v = bo[e + 1];
            float2 rA = make_float2((acc[mf][nf][0] + b0v) * mkA,
                                    (acc[mf][nf][1] + b1v) * mkA);
            float2 rB = make_float2((acc[mf][nf][2] + b0v) * mkB,
                                    (acc[mf][nf][3] + b1v) * mkB);
            *(float2*)&out[(size_t)ntA * DMODEL + e] = rA;
            *(float2*)&out[(size_t)ntB * DMODEL + e] = rB;
        }
    }
}

// ---------------- launch ----------------
extern "C" void kernel_launch(void* const* d_in, const int* in_sizes, int n_in,
                              void* d_out, int out_size) {
    const float* h  = (const float*)d_in[0];
    const void*  pm = d_in[1];
    const float* Wq = (const float*)d_in[2];
    const float* bq = (const float*)d_in[3];
    const float* Wk = (const float*)d_in[4];
    const float* bk = (const float*)d_in[5];
    const float* Wv = (const float*)d_in[6];
    const float* bv = (const float*)d_in[7];
    const float* Wo = (const float*)d_in[8];
    const float* bo = (const float*)d_in[9];
    float* out = (float*)d_out;

    mask_convert<<<1, 256>>>((const unsigned int*)pm, NTOK);
    bias_init<<<8, 256>>>();

    cudaFuncSetAttribute(qkv_gemm, cudaFuncAttributeMaxDynamicSharedMemorySize, GEMM_SMEM);
    cudaFuncSetAttribute(oproj_gemm, cudaFuncAttributeMaxDynamicSharedMemorySize, GEMM_SMEM);
    cudaFuncSetAttribute(attn_kernel, cudaFuncAttributeMaxDynamicSharedMemorySize, ATT_SMEM);

    dim3 g1(DMODEL / 128, NTOK / 128, 3);
    qkv_gemm<<<g1, 256, GEMM_SMEM>>>(h, Wq, bq, Wk, bk, Wv, bv);

    dim3 g2(M / 256, BH);
    attn_kernel<<<g2, 256, ATT_SMEM>>>();

    dim3 g3(DMODEL / 128, NTOK / 128);
    oproj_gemm<<<g3, 256, GEMM_SMEM>>>(Wo, bo, out);
}

// round 8
// speedup vs baseline: 8.0798x; 1.3015x over previous
#include <cuda_runtime.h>
#include <math.h>

#define B 4
#define M 2048
#define DMODEL 512
#define NHEAD 8
#define DHEAD 64
#define NTOK (B*M)          // 8192
#define BH (B*NHEAD)        // 32

// ---------------- scratch (device globals) ----------------
__device__ float g_x[NTOK * DMODEL];     // h, tf32-rounded
__device__ float g_wq[DMODEL * DMODEL];  // weights, tf32-rounded
__device__ float g_wk[DMODEL * DMODEL];
__device__ float g_wv[DMODEL * DMODEL];
__device__ float g_wo[DMODEL * DMODEL];
__device__ float g_q[BH * M * DHEAD];    // [b,h,m,dh], tf32-rounded, pre-scaled 1/8
__device__ float g_k[BH * M * DHEAD];    // [b,h,m,dh] tf32-rounded
__device__ float g_v[BH * DHEAD * M];    // [b,h,dh,m] TRANSPOSED, tf32-rounded
__device__ float g_ao[NTOK * DMODEL];    // attention output [b,m,d], tf32-rounded
__device__ float g_bias[M];              // log(exp(-d)+1e-12)
__device__ int   g_mask[NTOK];
__device__ unsigned g_mbits[NTOK / 32];  // packed mask bits

// ---------------- ptx helpers ----------------
__device__ __forceinline__ unsigned smem_u32(const void* p) {
    return (unsigned)__cvta_generic_to_shared(p);
}
__device__ __forceinline__ void cp16(unsigned d, const void* s) {
    asm volatile("cp.async.cg.shared.global [%0],[%1],16;\n" :: "r"(d), "l"(s) : "memory");
}
__device__ __forceinline__ void cp_commit() {
    asm volatile("cp.async.commit_group;\n" ::: "memory");
}
template<int N> __device__ __forceinline__ void cp_wait() {
    asm volatile("cp.async.wait_group %0;\n" :: "n"(N) : "memory");
}
__device__ __forceinline__ unsigned f2tf(float f) {
    unsigned u; asm("cvt.rna.tf32.f32 %0,%1;" : "=r"(u) : "f"(f)); return u;
}
__device__ __forceinline__ float f2tff(float f) { return __uint_as_float(f2tf(f)); }
__device__ __forceinline__ void mma8(float* c, const unsigned* a, const unsigned* b) {
    asm volatile(
        "mma.sync.aligned.m16n8k8.row.col.f32.tf32.tf32.f32 "
        "{%0,%1,%2,%3},{%4,%5,%6,%7},{%8,%9},{%0,%1,%2,%3};\n"
        : "+f"(c[0]), "+f"(c[1]), "+f"(c[2]), "+f"(c[3])
        : "r"(a[0]), "r"(a[1]), "r"(a[2]), "r"(a[3]), "r"(b[0]), "r"(b[1]));
}
__device__ __forceinline__ void ldsm4(unsigned& r0, unsigned& r1, unsigned& r2, unsigned& r3,
                                      unsigned addr) {
    asm volatile("ldmatrix.sync.aligned.m8n8.x4.shared.b16 {%0,%1,%2,%3},[%4];\n"
                 : "=r"(r0), "=r"(r1), "=r"(r2), "=r"(r3) : "r"(addr));
}

// ---------------- mask dtype sniff + convert + bit-pack ----------------
__global__ void mask_convert(const unsigned int* __restrict__ w, int n) {
    __shared__ int not01, not0f;
    if (threadIdx.x == 0) { not01 = 0; not0f = 0; }
    __syncthreads();
    int b01 = 0, b0f = 0;
    for (int i = threadIdx.x; i < 2048; i += blockDim.x) {
        unsigned v = w[i];
        if (v > 1u) b01 = 1;
        if (v != 0u && v != 0x3F800000u) b0f = 1;
    }
    if (b01) atomicOr(&not01, 1);
    if (b0f) atomicOr(&not0f, 1);
    __syncthreads();
    int mode = (!not01) ? 1 : ((!not0f) ? 2 : 0); // 1=int32, 2=float32, 0=uint8
    for (int i = threadIdx.x; i < n; i += blockDim.x) {
        int v;
        if (mode == 1)      v = (((const int*)w)[i] != 0);
        else if (mode == 2) v = (((const float*)w)[i] != 0.0f);
        else                v = (((const unsigned char*)w)[i] != 0);
        g_mask[i] = v;
    }
    __syncthreads();
    for (int wi = threadIdx.x; wi < n / 32; wi += blockDim.x) {
        unsigned bits = 0;
        for (int k = 0; k < 32; k++) bits |= (g_mask[wi * 32 + k] ? 1u : 0u) << k;
        g_mbits[wi] = bits;
    }
}

__global__ void bias_init() {
    int i = blockIdx.x * blockDim.x + threadIdx.x;
    if (i < M) g_bias[i] = logf(expf(-(float)i) + 1e-12f);
}

// ---------------- pre-round inputs to tf32 ----------------
__global__ void prep_round(const float* __restrict__ X,
                           const float* __restrict__ Wq, const float* __restrict__ Wk,
                           const float* __restrict__ Wv, const float* __restrict__ Wo) {
    int gid = blockIdx.x * blockDim.x + threadIdx.x;
    int stride = gridDim.x * blockDim.x;
    for (int i = gid; i < NTOK * DMODEL; i += stride) g_x[i] = f2tff(X[i]);
    for (int i = gid; i < DMODEL * DMODEL; i += stride) {
        g_wq[i] = f2tff(Wq[i]);
        g_wk[i] = f2tff(Wk[i]);
        g_wv[i] = f2tff(Wv[i]);
        g_wo[i] = f2tff(Wo[i]);
    }
}

// ---------------- GEMM common: 128x128 tile, 4-stage cp.async, k-slab 16 ----------------
#define GK 16
#define GLD2 20
#define GSTG (128 * GLD2)                 // floats per matrix per stage
#define GEMM_SMEM (4 * 2 * GSTG * 4)      // 81920 bytes

// ---------------- QKV projection ----------------
__global__ __launch_bounds__(256, 2) void qkv_gemm(
    const float* __restrict__ bq, const float* __restrict__ bk, const float* __restrict__ bv)
{
    extern __shared__ float sm[];
    const int z = blockIdx.z;
    const float* Wg   = (z == 0) ? g_wq : (z == 1) ? g_wk : g_wv;
    const float* bias = (z == 0) ? bq : (z == 1) ? bk : bv;
    float* out        = (z == 0) ? g_q : (z == 1) ? g_k : g_v;
    const float oscale = (z == 0) ? 0.125f : 1.0f;

    const int t = threadIdx.x, warp = t >> 5, lane = t & 31;
    const int q = lane & 3;
    const int wm = warp >> 1, wn = warp & 1;
    const int n0 = blockIdx.y << 7, e0 = blockIdx.x << 7;

    const int arow  = (lane & 7) + ((lane >> 3) & 1) * 8;
    const int acol4 = (lane >> 4) << 2;
    const int brow  = ((lane >> 4) << 3) + (lane & 7);
    const int bcol4 = ((lane >> 3) & 1) << 2;

    auto stage = [&](int it) {
        int kk = it * GK;
        float* base = sm + (it & 3) * 2 * GSTG;
#pragma unroll
        for (int j = 0; j < 2; j++) {
            int idx = t + j * 256;
            int row = idx >> 2, c16 = idx & 3;
            cp16(smem_u32(base + row * GLD2) + c16 * 16,
                 g_x + (size_t)(n0 + row) * DMODEL + kk + c16 * 4);
            cp16(smem_u32(base + GSTG + row * GLD2) + c16 * 16,
                 Wg + (size_t)(e0 + row) * DMODEL + kk + c16 * 4);
        }
        cp_commit();
    };

    stage(0); stage(1); stage(2);
    float acc[2][8][4] = {};
    for (int it = 0; it < 32; it++) {
        cp_wait<2>();
        __syncthreads();
        if (it + 3 < 32) stage(it + 3); else cp_commit();
        float* base = sm + (it & 3) * 2 * GSTG;
        const unsigned xa = smem_u32(base) + (unsigned)(((wm * 32 + arow) * GLD2 + acol4) * 4);
        const unsigned wa = smem_u32(base + GSTG) + (unsigned)(((wn * 64 + brow) * GLD2 + bcol4) * 4);
#pragma unroll
        for (int kc = 0; kc < 2; kc++) {
            unsigned af[2][4], bf[8][2];
#pragma unroll
            for (int mf = 0; mf < 2; mf++)
                ldsm4(af[mf][0], af[mf][1], af[mf][2], af[mf][3],
                      xa + (unsigned)((mf * 16 * GLD2 + kc * 8) * 4));
#pragma unroll
            for (int np = 0; np < 4; np++) {
                unsigned r0, r1, r2, r3;
                ldsm4(r0, r1, r2, r3, wa + (unsigned)((np * 16 * GLD2 + kc * 8) * 4));
                bf[2 * np][0] = r0;     bf[2 * np][1] = r1;
                bf[2 * np + 1][0] = r2; bf[2 * np + 1][1] = r3;
            }
#pragma unroll
            for (int mf = 0; mf < 2; mf++)
#pragma unroll
                for (int nf = 0; nf < 8; nf++) mma8(acc[mf][nf], af[mf], bf[nf]);
        }
    }

    // epilogue: direct to [b,h,m,dh] (V transposed), tf32-rounded
    const int g = lane >> 2;
#pragma unroll
    for (int mf = 0; mf < 2; mf++) {
        int ntA = n0 + wm * 32 + mf * 16 + g;
        int ntB = ntA + 8;
#pragma unroll
        for (int nf = 0; nf < 8; nf++) {
            int e = e0 + wn * 64 + nf * 8 + 2 * q;
            int hh = e >> 6, dh = e & 63;
            float b0v = bias[e], b1v = bias[e + 1];
            float vA0 = f2tff((acc[mf][nf][0] + b0v) * oscale);
            float vA1 = f2tff((acc[mf][nf][1] + b1v) * oscale);
            float vB0 = f2tff((acc[mf][nf][2] + b0v) * oscale);
            float vB1 = f2tff((acc[mf][nf][3] + b1v) * oscale);
            int bA = ntA >> 11, mA = ntA & 2047;
            int bB = ntB >> 11, mB = ntB & 2047;
            if (z == 2) {
                size_t baseA = ((size_t)bA * 8 + hh) * DHEAD;
                size_t baseB = ((size_t)bB * 8 + hh) * DHEAD;
                out[(baseA + dh) * M + mA]     = vA0;
                out[(baseA + dh + 1) * M + mA] = vA1;
                out[(baseB + dh) * M + mB]     = vB0;
                out[(baseB + dh + 1) * M + mB] = vB1;
            } else {
                *(float2*)&out[(((size_t)bA * 8 + hh) * M + mA) * DHEAD + dh] = make_float2(vA0, vA1);
                *(float2*)&out[(((size_t)bB * 8 + hh) * M + mB) * DHEAD + dh] = make_float2(vB0, vB1);
            }
        }
    }
}

// ---------------- attention: banded, 128-row Q tile, 16 rows/warp, 2 blocks/SM ----------------
#define KLD 68
#define VLD 68
#define PLD 68
// floats: K 2*64*68 + V 2*64*68 + P 8*16*68 + bias 256 + mbits 64
#define ATT_SMEM ((2*64*KLD + 2*64*VLD + 8*16*PLD + 256 + 64) * 4)   // 105728

__global__ __launch_bounds__(256, 2) void attn_kernel() {
    extern __shared__ float sm[];
    float* Ks0    = sm;                                   // [2][64][KLD]
    float* Vt0    = sm + 2 * 64 * KLD;                    // [2][64][VLD], row=d, col=key
    float* Pw_all = sm + 2 * 64 * KLD + 2 * 64 * VLD;     // [8][16][PLD]
    float* sbias  = Pw_all + 8 * 16 * PLD;                // [256] band window
    unsigned* mbw = (unsigned*)(sbias + 256);             // [64]

    const int t = threadIdx.x, warp = t >> 5, lane = t & 31;
    const int g = lane >> 2, q = lane & 3;
    const int bh = blockIdx.y, b = bh >> 3, hh = bh & 7;
    const int m0 = blockIdx.x << 7;                        // 128-row Q tile
    const float* qb = g_q + (size_t)bh * M * DHEAD;
    const float* kb = g_k + (size_t)bh * M * DHEAD;
    const float* vbT = g_v + (size_t)bh * DHEAD * M;

    sbias[t] = g_bias[t];                                  // t<256 covers |d|<=191
    if (t < 64) mbw[t] = g_mbits[b * 64 + t];

    // Q fragments, resident (16 rows/warp)
    const int mw = m0 + warp * 16;
    unsigned qf[8][4];
    {
        const float* q0 = qb + (size_t)(mw + g) * DHEAD;
        const float* q1 = qb + (size_t)(mw + g + 8) * DHEAD;
#pragma unroll
        for (int kc = 0; kc < 8; kc++) {
            qf[kc][0] = __float_as_uint(q0[kc * 8 + q]);
            qf[kc][1] = __float_as_uint(q1[kc * 8 + q]);
            qf[kc][2] = __float_as_uint(q0[kc * 8 + q + 4]);
            qf[kc][3] = __float_as_uint(q1[kc * 8 + q + 4]);
        }
    }

    float oacc[8][4] = {};
    float l0 = 0.0f, l1 = 0.0f;

    const int brow  = ((lane >> 4) << 3) + (lane & 7);
    const int bcol4 = ((lane >> 3) & 1) << 2;
    const unsigned kfb = (unsigned)((brow * KLD + bcol4) * 4);
    const unsigned vfb = (unsigned)((brow * VLD + bcol4) * 4);
    const int prow  = (lane & 7) + ((lane >> 3) & 1) * 8;
    const int pcol4 = (lane >> 4) << 2;
    float* Pw = Pw_all + warp * 16 * PLD;
    const unsigned pa_base = smem_u32(Pw) + (unsigned)((prow * PLD + pcol4) * 4);
    const unsigned ks_base = smem_u32(Ks0);
    const unsigned vs_base = smem_u32(Vt0);

    auto stage = [&](int tile, int buf) {
        const float* ksrc = kb + (size_t)(tile * 64) * DHEAD;
        const float* vsrc = vbT + tile * 64;
        float* kd = Ks0 + buf * 64 * KLD;
        float* vd = Vt0 + buf * 64 * VLD;
#pragma unroll
        for (int j = 0; j < 4; j++) {
            int ck = t + j * 256;                  // 0..1023
            int row = ck >> 4, c16 = ck & 15;
            cp16(smem_u32(kd + row * KLD) + c16 * 16, ksrc + row * 64 + c16 * 4);
            cp16(smem_u32(vd + row * VLD) + c16 * 16, vsrc + (size_t)row * M + c16 * 4);
        }
    };

    // banded tile range: keys within +-64 of [m0, m0+127]
    const int tlo = max(0, (m0 >> 6) - 1);
    const int thi = min(M / 64 - 1, (m0 >> 6) + 2);

    stage(tlo, 0); cp_commit();

    for (int tile = tlo; tile <= thi; tile++) {
        const int bufi = (tile - tlo) & 1;
        if (tile < thi) { stage(tile + 1, bufi ^ 1); cp_commit(); cp_wait<1>(); }
        else cp_wait<0>();
        __syncthreads();

        const int n0 = tile << 6;
        if (n0 <= mw + 79 && n0 + 63 >= mw - 64) {   // per-warp band check
            const unsigned kbuf = ks_base + bufi * (64 * KLD * 4) + kfb;
            const unsigned vbuf = vs_base + bufi * (64 * VLD * 4) + vfb;

            // ---- S = Q K^T ----
            float sacc[8][4] = {};
#pragma unroll
            for (int kc = 0; kc < 8; kc++) {
                unsigned bb[8][2];
#pragma unroll
                for (int np = 0; np < 4; np++) {
                    unsigned r0, r1, r2, r3;
                    ldsm4(r0, r1, r2, r3, kbuf + np * (16 * KLD * 4) + kc * 32);
                    bb[2 * np][0] = r0;     bb[2 * np][1] = r1;
                    bb[2 * np + 1][0] = r2; bb[2 * np + 1][1] = r3;
                }
#pragma unroll
                for (int nf = 0; nf < 8; nf++) mma8(sacc[nf], qf[kc], bb[nf]);
            }

            // ---- softmax (static max) + P store ----
            const unsigned w0 = mbw[tile * 2], w1 = mbw[tile * 2 + 1];
            const int mg0 = mw + g, mg1 = mg0 + 8;
#pragma unroll
            for (int nf = 0; nf < 8; nf++) {
                int off = nf * 8 + 2 * q;
                unsigned wsel = (nf < 4) ? w0 : w1;
                int sh = off & 31;
                bool v0m = (wsel >> sh) & 1;
                bool v1m = (wsel >> (sh + 1)) & 1;
                int n_ = n0 + off;
                int d00 = abs(mg0 - n_), d01 = abs(mg0 - n_ - 1);
                int d10 = abs(mg1 - n_), d11 = abs(mg1 - n_ - 1);
                float p0 = v0m ? __expf(sacc[nf][0] + sbias[d00]) : 0.0f;
                float p1 = v1m ? __expf(sacc[nf][1] + sbias[d01]) : 0.0f;
                float p2 = v0m ? __expf(sacc[nf][2] + sbias[d10]) : 0.0f;
                float p3 = v1m ? __expf(sacc[nf][3] + sbias[d11]) : 0.0f;
                p0 = f2tff(p0); p1 = f2tff(p1); p2 = f2tff(p2); p3 = f2tff(p3);
                l0 += p0 + p1; l1 += p2 + p3;
                *(float2*)&Pw[g * PLD + off]       = make_float2(p0, p1);
                *(float2*)&Pw[(g + 8) * PLD + off] = make_float2(p2, p3);
            }
            __syncwarp();

            // ---- O += P V ----
#pragma unroll
            for (int kc = 0; kc < 8; kc++) {
                unsigned pa[4];
                ldsm4(pa[0], pa[1], pa[2], pa[3], pa_base + kc * 32);
                unsigned vv[8][2];
#pragma unroll
                for (int dp = 0; dp < 4; dp++) {
                    unsigned r0, r1, r2, r3;
                    ldsm4(r0, r1, r2, r3, vbuf + dp * (16 * VLD * 4) + kc * 32);
                    vv[2 * dp][0] = r0;     vv[2 * dp][1] = r1;
                    vv[2 * dp + 1][0] = r2; vv[2 * dp + 1][1] = r3;
                }
#pragma unroll
                for (int df = 0; df < 8; df++) mma8(oacc[df], pa, vv[df]);
            }
        }
        __syncthreads();
    }

    // ---- epilogue: quad-reduce row sums, normalize, write tf32-rounded [b,m,d] ----
    l0 += __shfl_xor_sync(0xffffffffu, l0, 1);
    l0 += __shfl_xor_sync(0xffffffffu, l0, 2);
    l1 += __shfl_xor_sync(0xffffffffu, l1, 1);
    l1 += __shfl_xor_sync(0xffffffffu, l1, 2);
    float i0 = 1.0f / fmaxf(l0, 1e-30f);
    float i1 = 1.0f / fmaxf(l1, 1e-30f);
    float* ob = g_ao + (size_t)b * M * DMODEL + (size_t)hh * DHEAD;
#pragma unroll
    for (int df = 0; df < 8; df++) {
        *(float2*)&ob[(size_t)(mw + g) * DMODEL + df * 8 + 2 * q] =
            make_float2(f2tff(oacc[df][0] * i0), f2tff(oacc[df][1] * i0));
        *(float2*)&ob[(size_t)(mw + g + 8) * DMODEL + df * 8 + 2 * q] =
            make_float2(f2tff(oacc[df][2] * i1), f2tff(oacc[df][3] * i1));
    }
}

// ---------------- output projection + mask ----------------
__global__ __launch_bounds__(256, 2) void oproj_gemm(
    const float* __restrict__ bo, float* __restrict__ out)
{
    extern __shared__ float sm[];
    const int t = threadIdx.x, warp = t >> 5, lane = t & 31;
    const int q = lane & 3;
    const int wm = warp >> 1, wn = warp & 1;
    const int n0 = blockIdx.y << 7, e0 = blockIdx.x << 7;

    const int arow  = (lane & 7) + ((lane >> 3) & 1) * 8;
    const int acol4 = (lane >> 4) << 2;
    const int brow  = ((lane >> 4) << 3) + (lane & 7);
    const int bcol4 = ((lane >> 3) & 1) << 2;

    auto stage = [&](int it) {
        int kk = it * GK;
        float* base = sm + (it & 3) * 2 * GSTG;
#pragma unroll
        for (int j = 0; j < 2; j++) {
            int idx = t + j * 256;
            int row = idx >> 2, c16 = idx & 3;
            cp16(smem_u32(base + row * GLD2) + c16 * 16,
                 g_ao + (size_t)(n0 + row) * DMODEL + kk + c16 * 4);
            cp16(smem_u32(base + GSTG + row * GLD2) + c16 * 16,
                 g_wo + (size_t)(e0 + row) * DMODEL + kk + c16 * 4);
        }
        cp_commit();
    };

    stage(0); stage(1); stage(2);
    float acc[2][8][4] = {};
    for (int it = 0; it < 32; it++) {
        cp_wait<2>();
        __syncthreads();
        if (it + 3 < 32) stage(it + 3); else cp_commit();
        float* base = sm + (it & 3) * 2 * GSTG;
        const unsigned xa = smem_u32(base) + (unsigned)(((wm * 32 + arow) * GLD2 + acol4) * 4);
        const unsigned wa = smem_u32(base + GSTG) + (unsigned)(((wn * 64 + brow) * GLD2 + bcol4) * 4);
#pragma unroll
        for (int kc = 0; kc < 2; kc++) {
            unsigned af[2][4], bf[8][2];
#pragma unroll
            for (int mf = 0; mf < 2; mf++)
                ldsm4(af[mf][0], af[mf][1], af[mf][2], af[mf][3],
                      xa + (unsigned)((mf * 16 * GLD2 + kc * 8) * 4));
#pragma unroll
            for (int np = 0; np < 4; np++) {
                unsigned r0, r1, r2, r3;
                ldsm4(r0, r1, r2, r3, wa + (unsigned)((np * 16 * GLD2 + kc * 8) * 4));
                bf[2 * np][0] = r0;     bf[2 * np][1] = r1;
                bf[2 * np + 1][0] = r2; bf[2 * np + 1][1] = r3;
            }
#pragma unroll
            for (int mf = 0; mf < 2; mf++)
#pragma unroll
                for (int nf = 0; nf < 8; nf++) mma8(acc[mf][nf], af[mf], bf[nf]);
        }
    }

    const int g = lane >> 2;
#pragma unroll
    for (int mf = 0; mf < 2; mf++) {
        int ntA = n0 + wm * 32 + mf * 16 + g;
        int ntB = ntA + 8;
        float mkA = (float)g_mask[ntA];
        float mkB = (float)g_mask[ntB];
#pragma unroll
        for (int nf = 0; nf < 8; nf++) {
            int e = e0 + wn * 64 + nf * 8 + 2 * q;
            float b0v = bo[e], b1v = bo[e + 1];
            float2 rA = make_float2((acc[mf][nf][0] + b0v) * mkA,
                                    (acc[mf][nf][1] + b1v) * mkA);
            float2 rB = make_float2((acc[mf][nf][2] + b0v) * mkB,
                                    (acc[mf][nf][3] + b1v) * mkB);
            *(float2*)&out[(size_t)ntA * DMODEL + e] = rA;
            *(float2*)&out[(size_t)ntB * DMODEL + e] = rB;
        }
    }
}

// ---------------- launch ----------------
extern "C" void kernel_launch(void* const* d_in, const int* in_sizes, int n_in,
                              void* d_out, int out_size) {
    const float* h  = (const float*)d_in[0];
    const void*  pm = d_in[1];
    const float* Wq = (const float*)d_in[2];
    const float* bq = (const float*)d_in[3];
    const float* Wk = (const float*)d_in[4];
    const float* bk = (const float*)d_in[5];
    const float* Wv = (const float*)d_in[6];
    const float* bv = (const float*)d_in[7];
    const float* Wo = (const float*)d_in[8];
    const float* bo = (const float*)d_in[9];
    float* out = (float*)d_out;

    mask_convert<<<1, 256>>>((const unsigned int*)pm, NTOK);
    bias_init<<<8, 256>>>();
    prep_round<<<512, 256>>>(h, Wq, Wk, Wv, Wo);

    cudaFuncSetAttribute(qkv_gemm, cudaFuncAttributeMaxDynamicSharedMemorySize, GEMM_SMEM);
    cudaFuncSetAttribute(oproj_gemm, cudaFuncAttributeMaxDynamicSharedMemorySize, GEMM_SMEM);
    cudaFuncSetAttribute(attn_kernel, cudaFuncAttributeMaxDynamicSharedMemorySize, ATT_SMEM);

    dim3 g1(DMODEL / 128, NTOK / 128, 3);
    qkv_gemm<<<g1, 256, GEMM_SMEM>>>(bq, bk, bv);

    dim3 g2(M / 128, BH);
    attn_kernel<<<g2, 256, ATT_SMEM>>>();

    dim3 g3(DMODEL / 128, NTOK / 128);
    oproj_gemm<<<g3, 256, GEMM_SMEM>>>(bo, out);
}

// round 9
// speedup vs baseline: 8.6137x; 1.0661x over previous
#include <cuda_runtime.h>
#include <math.h>

#define B 4
#define M 2048
#define DMODEL 512
#define NHEAD 8
#define DHEAD 64
#define NTOK (B*M)          // 8192
#define BH (B*NHEAD)        // 32

// ---------------- scratch (device globals) ----------------
__device__ float g_x[NTOK * DMODEL];     // h, tf32-rounded
__device__ float g_wq[DMODEL * DMODEL];  // weights, tf32-rounded
__device__ float g_wk[DMODEL * DMODEL];
__device__ float g_wv[DMODEL * DMODEL];
__device__ float g_wo[DMODEL * DMODEL];
__device__ float g_q[BH * M * DHEAD];    // [b,h,m,dh], tf32-rounded, pre-scaled 1/8
__device__ float g_k[BH * M * DHEAD];    // [b,h,m,dh] tf32-rounded
__device__ float g_v[BH * DHEAD * M];    // [b,h,dh,m] TRANSPOSED, tf32-rounded
__device__ float g_ao[NTOK * DMODEL];    // attention output [b,m,d], tf32-rounded
__device__ float g_bias[M];              // log(exp(-d)+1e-12)
__device__ int   g_mask[NTOK];
__device__ unsigned g_mbits[NTOK / 32];  // packed mask bits

// ---------------- ptx helpers ----------------
__device__ __forceinline__ unsigned smem_u32(const void* p) {
    return (unsigned)__cvta_generic_to_shared(p);
}
__device__ __forceinline__ void cp16(unsigned d, const void* s) {
    asm volatile("cp.async.cg.shared.global [%0],[%1],16;\n" :: "r"(d), "l"(s) : "memory");
}
__device__ __forceinline__ void cp_commit() {
    asm volatile("cp.async.commit_group;\n" ::: "memory");
}
template<int N> __device__ __forceinline__ void cp_wait() {
    asm volatile("cp.async.wait_group %0;\n" :: "n"(N) : "memory");
}
__device__ __forceinline__ unsigned f2tf(float f) {
    unsigned u; asm("cvt.rna.tf32.f32 %0,%1;" : "=r"(u) : "f"(f)); return u;
}
__device__ __forceinline__ float f2tff(float f) { return __uint_as_float(f2tf(f)); }
__device__ __forceinline__ void mma8(float* c, const unsigned* a, const unsigned* b) {
    asm volatile(
        "mma.sync.aligned.m16n8k8.row.col.f32.tf32.tf32.f32 "
        "{%0,%1,%2,%3},{%4,%5,%6,%7},{%8,%9},{%0,%1,%2,%3};\n"
        : "+f"(c[0]), "+f"(c[1]), "+f"(c[2]), "+f"(c[3])
        : "r"(a[0]), "r"(a[1]), "r"(a[2]), "r"(a[3]), "r"(b[0]), "r"(b[1]));
}
__device__ __forceinline__ void ldsm4(unsigned& r0, unsigned& r1, unsigned& r2, unsigned& r3,
                                      unsigned addr) {
    asm volatile("ldmatrix.sync.aligned.m8n8.x4.shared.b16 {%0,%1,%2,%3},[%4];\n"
                 : "=r"(r0), "=r"(r1), "=r"(r2), "=r"(r3) : "r"(addr));
}

// ---------------- mask dtype sniff + convert + bit-pack ----------------
__global__ void mask_convert(const unsigned int* __restrict__ w, int n) {
    __shared__ int not01, not0f;
    if (threadIdx.x == 0) { not01 = 0; not0f = 0; }
    __syncthreads();
    int b01 = 0, b0f = 0;
    for (int i = threadIdx.x; i < 2048; i += blockDim.x) {
        unsigned v = w[i];
        if (v > 1u) b01 = 1;
        if (v != 0u && v != 0x3F800000u) b0f = 1;
    }
    if (b01) atomicOr(&not01, 1);
    if (b0f) atomicOr(&not0f, 1);
    __syncthreads();
    int mode = (!not01) ? 1 : ((!not0f) ? 2 : 0); // 1=int32, 2=float32, 0=uint8
    for (int i = threadIdx.x; i < n; i += blockDim.x) {
        int v;
        if (mode == 1)      v = (((const int*)w)[i] != 0);
        else if (mode == 2) v = (((const float*)w)[i] != 0.0f);
        else                v = (((const unsigned char*)w)[i] != 0);
        g_mask[i] = v;
    }
    __syncthreads();
    for (int wi = threadIdx.x; wi < n / 32; wi += blockDim.x) {
        unsigned bits = 0;
        for (int k = 0; k < 32; k++) bits |= (g_mask[wi * 32 + k] ? 1u : 0u) << k;
        g_mbits[wi] = bits;
    }
}

__global__ void bias_init() {
    int i = blockIdx.x * blockDim.x + threadIdx.x;
    if (i < M) g_bias[i] = logf(expf(-(float)i) + 1e-12f);
}

// ---------------- pre-round inputs to tf32 ----------------
__global__ void prep_round(const float* __restrict__ X,
                           const float* __restrict__ Wq, const float* __restrict__ Wk,
                           const float* __restrict__ Wv, const float* __restrict__ Wo) {
    int gid = blockIdx.x * blockDim.x + threadIdx.x;
    int stride = gridDim.x * blockDim.x;
    for (int i = gid; i < NTOK * DMODEL; i += stride) g_x[i] = f2tff(X[i]);
    for (int i = gid; i < DMODEL * DMODEL; i += stride) {
        g_wq[i] = f2tff(Wq[i]);
        g_wk[i] = f2tff(Wk[i]);
        g_wv[i] = f2tff(Wv[i]);
        g_wo[i] = f2tff(Wo[i]);
    }
}

// ---------------- GEMM common: 128x128 tile, k-slab 32, 2-stage cp.async ----------------
#define GK 32
#define GLD 36
#define GSTG (128 * GLD)                  // floats per matrix per stage (4608)
#define GEMM_SMEM (2 * 2 * GSTG * 4)      // 73728 bytes

// ---------------- QKV projection ----------------
__global__ __launch_bounds__(256, 2) void qkv_gemm(
    const float* __restrict__ bq, const float* __restrict__ bk, const float* __restrict__ bv)
{
    extern __shared__ float sm[];
    const int z = blockIdx.z;
    const float* Wg   = (z == 0) ? g_wq : (z == 1) ? g_wk : g_wv;
    const float* bias = (z == 0) ? bq : (z == 1) ? bk : bv;
    float* out        = (z == 0) ? g_q : (z == 1) ? g_k : g_v;
    const float oscale = (z == 0) ? 0.125f : 1.0f;

    const int t = threadIdx.x, warp = t >> 5, lane = t & 31;
    const int q = lane & 3;
    const int wm = warp >> 1, wn = warp & 1;
    const int n0 = blockIdx.y << 7, e0 = blockIdx.x << 7;

    const int arow  = (lane & 7) + ((lane >> 3) & 1) * 8;
    const int acol4 = (lane >> 4) << 2;
    const int brow  = ((lane >> 4) << 3) + (lane & 7);
    const int bcol4 = ((lane >> 3) & 1) << 2;

    const int srow = t >> 3, sc16 = t & 7;   // 128 rows x 8 float4-cols

    auto stage = [&](int it) {
        int kk = it * GK;
        float* base = sm + (it & 1) * 2 * GSTG;
#pragma unroll
        for (int j = 0; j < 4; j++) {
            int row = srow + j * 32;
            cp16(smem_u32(base + row * GLD) + sc16 * 16,
                 g_x + (size_t)(n0 + row) * DMODEL + kk + sc16 * 4);
            cp16(smem_u32(base + GSTG + row * GLD) + sc16 * 16,
                 Wg + (size_t)(e0 + row) * DMODEL + kk + sc16 * 4);
        }
        cp_commit();
    };

    stage(0);
    float acc[2][8][4] = {};
    for (int it = 0; it < 16; it++) {
        if (it < 15) { stage(it + 1); cp_wait<1>(); }
        else cp_wait<0>();
        __syncthreads();
        float* base = sm + (it & 1) * 2 * GSTG;
        const unsigned xa = smem_u32(base) + (unsigned)(((wm * 32 + arow) * GLD + acol4) * 4);
        const unsigned wa = smem_u32(base + GSTG) + (unsigned)(((wn * 64 + brow) * GLD + bcol4) * 4);
#pragma unroll
        for (int kc = 0; kc < 4; kc++) {
            unsigned af[2][4], bf[8][2];
#pragma unroll
            for (int mf = 0; mf < 2; mf++)
                ldsm4(af[mf][0], af[mf][1], af[mf][2], af[mf][3],
                      xa + (unsigned)((mf * 16 * GLD + kc * 8) * 4));
#pragma unroll
            for (int np = 0; np < 4; np++) {
                unsigned r0, r1, r2, r3;
                ldsm4(r0, r1, r2, r3, wa + (unsigned)((np * 16 * GLD + kc * 8) * 4));
                bf[2 * np][0] = r0;     bf[2 * np][1] = r1;
                bf[2 * np + 1][0] = r2; bf[2 * np + 1][1] = r3;
            }
#pragma unroll
            for (int mf = 0; mf < 2; mf++)
#pragma unroll
                for (int nf = 0; nf < 8; nf++) mma8(acc[mf][nf], af[mf], bf[nf]);
        }
        __syncthreads();
    }

    // epilogue: direct to [b,h,m,dh] (V transposed), tf32-rounded
    const int g = lane >> 2;
#pragma unroll
    for (int mf = 0; mf < 2; mf++) {
        int ntA = n0 + wm * 32 + mf * 16 + g;
        int ntB = ntA + 8;
#pragma unroll
        for (int nf = 0; nf < 8; nf++) {
            int e = e0 + wn * 64 + nf * 8 + 2 * q;
            int hh = e >> 6, dh = e & 63;
            float b0v = bias[e], b1v = bias[e + 1];
            float vA0 = f2tff((acc[mf][nf][0] + b0v) * oscale);
            float vA1 = f2tff((acc[mf][nf][1] + b1v) * oscale);
            float vB0 = f2tff((acc[mf][nf][2] + b0v) * oscale);
            float vB1 = f2tff((acc[mf][nf][3] + b1v) * oscale);
            int bA = ntA >> 11, mA = ntA & 2047;
            int bB = ntB >> 11, mB = ntB & 2047;
            if (z == 2) {
                size_t baseA = ((size_t)bA * 8 + hh) * DHEAD;
                size_t baseB = ((size_t)bB * 8 + hh) * DHEAD;
                out[(baseA + dh) * M + mA]     = vA0;
                out[(baseA + dh + 1) * M + mA] = vA1;
                out[(baseB + dh) * M + mB]     = vB0;
                out[(baseB + dh + 1) * M + mB] = vB1;
            } else {
                *(float2*)&out[(((size_t)bA * 8 + hh) * M + mA) * DHEAD + dh] = make_float2(vA0, vA1);
                *(float2*)&out[(((size_t)bB * 8 + hh) * M + mB) * DHEAD + dh] = make_float2(vB0, vB1);
            }
        }
    }
}

// ---------------- attention: banded, 128-row Q tile, 16 rows/warp, 2 blocks/SM ----------------
#define KLD 68
#define VLD 68
#define PLD 68
#define ATT_SMEM ((2*64*KLD + 2*64*VLD + 8*16*PLD + 256 + 64) * 4)   // 105728

__global__ __launch_bounds__(256, 2) void attn_kernel() {
    extern __shared__ float sm[];
    float* Ks0    = sm;                                   // [2][64][KLD]
    float* Vt0    = sm + 2 * 64 * KLD;                    // [2][64][VLD], row=d, col=key
    float* Pw_all = sm + 2 * 64 * KLD + 2 * 64 * VLD;     // [8][16][PLD]
    float* sbias  = Pw_all + 8 * 16 * PLD;                // [256] band window
    unsigned* mbw = (unsigned*)(sbias + 256);             // [64]

    const int t = threadIdx.x, warp = t >> 5, lane = t & 31;
    const int g = lane >> 2, q = lane & 3;
    const int bh = blockIdx.y, b = bh >> 3, hh = bh & 7;
    const int m0 = blockIdx.x << 7;                        // 128-row Q tile
    const float* qb = g_q + (size_t)bh * M * DHEAD;
    const float* kb = g_k + (size_t)bh * M * DHEAD;
    const float* vbT = g_v + (size_t)bh * DHEAD * M;

    sbias[t] = g_bias[t];
    if (t < 64) mbw[t] = g_mbits[b * 64 + t];

    const int mw = m0 + warp * 16;
    unsigned qf[8][4];
    {
        const float* q0 = qb + (size_t)(mw + g) * DHEAD;
        const float* q1 = qb + (size_t)(mw + g + 8) * DHEAD;
#pragma unroll
        for (int kc = 0; kc < 8; kc++) {
            qf[kc][0] = __float_as_uint(q0[kc * 8 + q]);
            qf[kc][1] = __float_as_uint(q1[kc * 8 + q]);
            qf[kc][2] = __float_as_uint(q0[kc * 8 + q + 4]);
            qf[kc][3] = __float_as_uint(q1[kc * 8 + q + 4]);
        }
    }

    float oacc[8][4] = {};
    float l0 = 0.0f, l1 = 0.0f;

    const int brow  = ((lane >> 4) << 3) + (lane & 7);
    const int bcol4 = ((lane >> 3) & 1) << 2;
    const unsigned kfb = (unsigned)((brow * KLD + bcol4) * 4);
    const unsigned vfb = (unsigned)((brow * VLD + bcol4) * 4);
    const int prow  = (lane & 7) + ((lane >> 3) & 1) * 8;
    const int pcol4 = (lane >> 4) << 2;
    float* Pw = Pw_all + warp * 16 * PLD;
    const unsigned pa_base = smem_u32(Pw) + (unsigned)((prow * PLD + pcol4) * 4);
    const unsigned ks_base = smem_u32(Ks0);
    const unsigned vs_base = smem_u32(Vt0);

    auto stage = [&](int tile, int buf) {
        const float* ksrc = kb + (size_t)(tile * 64) * DHEAD;
        const float* vsrc = vbT + tile * 64;
        float* kd = Ks0 + buf * 64 * KLD;
        float* vd = Vt0 + buf * 64 * VLD;
#pragma unroll
        for (int j = 0; j < 4; j++) {
            int ck = t + j * 256;
            int row = ck >> 4, c16 = ck & 15;
            cp16(smem_u32(kd + row * KLD) + c16 * 16, ksrc + row * 64 + c16 * 4);
            cp16(smem_u32(vd + row * VLD) + c16 * 16, vsrc + (size_t)row * M + c16 * 4);
        }
    };

    const int tlo = max(0, (m0 >> 6) - 1);
    const int thi = min(M / 64 - 1, (m0 >> 6) + 2);

    stage(tlo, 0); cp_commit();

    for (int tile = tlo; tile <= thi; tile++) {
        const int bufi = (tile - tlo) & 1;
        if (tile < thi) { stage(tile + 1, bufi ^ 1); cp_commit(); cp_wait<1>(); }
        else cp_wait<0>();
        __syncthreads();

        const int n0 = tile << 6;
        if (n0 <= mw + 79 && n0 + 63 >= mw - 64) {
            const unsigned kbuf = ks_base + bufi * (64 * KLD * 4) + kfb;
            const unsigned vbuf = vs_base + bufi * (64 * VLD * 4) + vfb;

            float sacc[8][4] = {};
#pragma unroll
            for (int kc = 0; kc < 8; kc++) {
                unsigned bb[8][2];
#pragma unroll
                for (int np = 0; np < 4; np++) {
                    unsigned r0, r1, r2, r3;
                    ldsm4(r0, r1, r2, r3, kbuf + np * (16 * KLD * 4) + kc * 32);
                    bb[2 * np][0] = r0;     bb[2 * np][1] = r1;
                    bb[2 * np + 1][0] = r2; bb[2 * np + 1][1] = r3;
                }
#pragma unroll
                for (int nf = 0; nf < 8; nf++) mma8(sacc[nf], qf[kc], bb[nf]);
            }

            const unsigned w0 = mbw[tile * 2], w1 = mbw[tile * 2 + 1];
            const int mg0 = mw + g, mg1 = mg0 + 8;
#pragma unroll
            for (int nf = 0; nf < 8; nf++) {
                int off = nf * 8 + 2 * q;
                unsigned wsel = (nf < 4) ? w0 : w1;
                int sh = off & 31;
                bool v0m = (wsel >> sh) & 1;
                bool v1m = (wsel >> (sh + 1)) & 1;
                int n_ = n0 + off;
                int d00 = abs(mg0 - n_), d01 = abs(mg0 - n_ - 1);
                int d10 = abs(mg1 - n_), d11 = abs(mg1 - n_ - 1);
                float p0 = v0m ? __expf(sacc[nf][0] + sbias[d00]) : 0.0f;
                float p1 = v1m ? __expf(sacc[nf][1] + sbias[d01]) : 0.0f;
                float p2 = v0m ? __expf(sacc[nf][2] + sbias[d10]) : 0.0f;
                float p3 = v1m ? __expf(sacc[nf][3] + sbias[d11]) : 0.0f;
                p0 = f2tff(p0); p1 = f2tff(p1); p2 = f2tff(p2); p3 = f2tff(p3);
                l0 += p0 + p1; l1 += p2 + p3;
                *(float2*)&Pw[g * PLD + off]       = make_float2(p0, p1);
                *(float2*)&Pw[(g + 8) * PLD + off] = make_float2(p2, p3);
            }
            __syncwarp();

#pragma unroll
            for (int kc = 0; kc < 8; kc++) {
                unsigned pa[4];
                ldsm4(pa[0], pa[1], pa[2], pa[3], pa_base + kc * 32);
                unsigned vv[8][2];
#pragma unroll
                for (int dp = 0; dp < 4; dp++) {
                    unsigned r0, r1, r2, r3;
                    ldsm4(r0, r1, r2, r3, vbuf + dp * (16 * VLD * 4) + kc * 32);
                    vv[2 * dp][0] = r0;     vv[2 * dp][1] = r1;
                    vv[2 * dp + 1][0] = r2; vv[2 * dp + 1][1] = r3;
                }
#pragma unroll
                for (int df = 0; df < 8; df++) mma8(oacc[df], pa, vv[df]);
            }
        }
        __syncthreads();
    }

    l0 += __shfl_xor_sync(0xffffffffu, l0, 1);
    l0 += __shfl_xor_sync(0xffffffffu, l0, 2);
    l1 += __shfl_xor_sync(0xffffffffu, l1, 1);
    l1 += __shfl_xor_sync(0xffffffffu, l1, 2);
    float i0 = 1.0f / fmaxf(l0, 1e-30f);
    float i1 = 1.0f / fmaxf(l1, 1e-30f);
    float* ob = g_ao + (size_t)b * M * DMODEL + (size_t)hh * DHEAD;
#pragma unroll
    for (int df = 0; df < 8; df++) {
        *(float2*)&ob[(size_t)(mw + g) * DMODEL + df * 8 + 2 * q] =
            make_float2(f2tff(oacc[df][0] * i0), f2tff(oacc[df][1] * i0));
        *(float2*)&ob[(size_t)(mw + g + 8) * DMODEL + df * 8 + 2 * q] =
            make_float2(f2tff(oacc[df][2] * i1), f2tff(oacc[df][3] * i1));
    }
}

// ---------------- output projection + mask ----------------
__global__ __launch_bounds__(256, 2) void oproj_gemm(
    const float* __restrict__ bo, float* __restrict__ out)
{
    extern __shared__ float sm[];
    const int t = threadIdx.x, warp = t >> 5, lane = t & 31;
    const int q = lane & 3;
    const int wm = warp >> 1, wn = warp & 1;
    const int n0 = blockIdx.y << 7, e0 = blockIdx.x << 7;

    const int arow  = (lane & 7) + ((lane >> 3) & 1) * 8;
    const int acol4 = (lane >> 4) << 2;
    const int brow  = ((lane >> 4) << 3) + (lane & 7);
    const int bcol4 = ((lane >> 3) & 1) << 2;

    const int srow = t >> 3, sc16 = t & 7;

    auto stage = [&](int it) {
        int kk = it * GK;
        float* base = sm + (it & 1) * 2 * GSTG;
#pragma unroll
        for (int j = 0; j < 4; j++) {
            int row = srow + j * 32;
            cp16(smem_u32(base + row * GLD) + sc16 * 16,
                 g_ao + (size_t)(n0 + row) * DMODEL + kk + sc16 * 4);
            cp16(smem_u32(base + GSTG + row * GLD) + sc16 * 16,
                 g_wo + (size_t)(e0 + row) * DMODEL + kk + sc16 * 4);
        }
        cp_commit();
    };

    stage(0);
    float acc[2][8][4] = {};
    for (int it = 0; it < 16; it++) {
        if (it < 15) { stage(it + 1); cp_wait<1>(); }
        else cp_wait<0>();
        __syncthreads();
        float* base = sm + (it & 1) * 2 * GSTG;
        const unsigned xa = smem_u32(base) + (unsigned)(((wm * 32 + arow) * GLD + acol4) * 4);
        const unsigned wa = smem_u32(base + GSTG) + (unsigned)(((wn * 64 + brow) * GLD + bcol4) * 4);
#pragma unroll
        for (int kc = 0; kc < 4; kc++) {
            unsigned af[2][4], bf[8][2];
#pragma unroll
            for (int mf = 0; mf < 2; mf++)
                ldsm4(af[mf][0], af[mf][1], af[mf][2], af[mf][3],
                      xa + (unsigned)((mf * 16 * GLD + kc * 8) * 4));
#pragma unroll
            for (int np = 0; np < 4; np++) {
                unsigned r0, r1, r2, r3;
                ldsm4(r0, r1, r2, r3, wa + (unsigned)((np * 16 * GLD + kc * 8) * 4));
                bf[2 * np][0] = r0;     bf[2 * np][1] = r1;
                bf[2 * np + 1][0] = r2; bf[2 * np + 1][1] = r3;
            }
#pragma unroll
            for (int mf = 0; mf < 2; mf++)
#pragma unroll
                for (int nf = 0; nf < 8; nf++) mma8(acc[mf][nf], af[mf], bf[nf]);
        }
        __syncthreads();
    }

    const int g = lane >> 2;
#pragma unroll
    for (int mf = 0; mf < 2; mf++) {
        int ntA = n0 + wm * 32 + mf * 16 + g;
        int ntB = ntA + 8;
        float mkA = (float)g_mask[ntA];
        float mkB = (float)g_mask[ntB];
#pragma unroll
        for (int nf = 0; nf < 8; nf++) {
            int e = e0 + wn * 64 + nf * 8 + 2 * q;
            float b0v = bo[e], b1v = bo[e + 1];
            float2 rA = make_float2((acc[mf][nf][0] + b0v) * mkA,
                                    (acc[mf][nf][1] + b1v) * mkA);
            float2 rB = make_float2((acc[mf][nf][2] + b0v) * mkB,
                                    (acc[mf][nf][3] + b1v) * mkB);
            *(float2*)&out[(size_t)ntA * DMODEL + e] = rA;
            *(float2*)&out[(size_t)ntB * DMODEL + e] = rB;
        }
    }
}

// ---------------- launch ----------------
extern "C" void kernel_launch(void* const* d_in, const int* in_sizes, int n_in,
                              void* d_out, int out_size) {
    const float* h  = (const float*)d_in[0];
    const void*  pm = d_in[1];
    const float* Wq = (const float*)d_in[2];
    const float* bq = (const float*)d_in[3];
    const float* Wk = (const float*)d_in[4];
    const float* bk = (const float*)d_in[5];
    const float* Wv = (const float*)d_in[6];
    const float* bv = (const float*)d_in[7];
    const float* Wo = (const float*)d_in[8];
    const float* bo = (const float*)d_in[9];
    float* out = (float*)d_out;

    mask_convert<<<1, 256>>>((const unsigned int*)pm, NTOK);
    bias_init<<<8, 256>>>();
    prep_round<<<512, 256>>>(h, Wq, Wk, Wv, Wo);

    cudaFuncSetAttribute(qkv_gemm, cudaFuncAttributeMaxDynamicSharedMemorySize, GEMM_SMEM);
    cudaFuncSetAttribute(oproj_gemm, cudaFuncAttributeMaxDynamicSharedMemorySize, GEMM_SMEM);
    cudaFuncSetAttribute(attn_kernel, cudaFuncAttributeMaxDynamicSharedMemorySize, ATT_SMEM);

    dim3 g1(DMODEL / 128, NTOK / 128, 3);
    qkv_gemm<<<g1, 256, GEMM_SMEM>>>(bq, bk, bv);

    dim3 g2(M / 128, BH);
    attn_kernel<<<g2, 256, ATT_SMEM>>>();

    dim3 g3(DMODEL / 128, NTOK / 128);
    oproj_gemm<<<g3, 256, GEMM_SMEM>>>(bo, out);
}